// round 1
// baseline (speedup 1.0000x reference)
#include <cuda_runtime.h>
#include <cuda_bf16.h>
#include <math.h>

// Problem constants
#define BB 8
#define TT 1024
#define CC 768
#define NH 12
#define HD 64
#define C3 (3*CC)   // 2304

// ---------------- scratch (no allocation allowed) ----------------
__device__ float g_qkv[BB * TT * C3];   // [B,T,3C]  75.5 MB
__device__ float g_y  [BB * TT * CC];   // [B,T,C]   25 MB

// ---------------- SGEMM: C[M,N] = A[M,K] @ W[K,N] + bias[N] ----------------
// BM=128, BN=128, BK=16, 256 threads, 8x8 microtile. M%128==0, N%128==0, K%16==0.
#define GBM 128
#define GBN 128
#define GBK 16

__global__ __launch_bounds__(256, 2)
void sgemm_bias_kernel(const float* __restrict__ A,
                       const float* __restrict__ W,
                       const float* __restrict__ bias,
                       float* __restrict__ Cout,
                       int M, int N, int K)
{
    __shared__ float As[GBK][GBM + 4];   // padded: stride 132 to soften transpose-store conflicts
    __shared__ float Ws[GBK][GBN];

    const int tid = threadIdx.x;          // 0..255
    const int tr  = tid / 16;             // 0..15 -> rows  tr*8..+7
    const int tc  = tid % 16;             // 0..15 -> cols  tc*8..+7
    const int m0  = blockIdx.y * GBM;
    const int n0  = blockIdx.x * GBN;

    float acc[8][8];
    #pragma unroll
    for (int i = 0; i < 8; i++)
        #pragma unroll
        for (int j = 0; j < 8; j++) acc[i][j] = 0.f;

    const int arow = tid / 4;             // 0..63
    const int acol = (tid % 4) * 4;       // 0,4,8,12
    const int wrow = tid / 32;            // 0..7
    const int wcol = (tid % 32) * 4;      // 0..124

    for (int k0 = 0; k0 < K; k0 += GBK) {
        // A tile: rows m0..+127, cols k0..+15  (store transposed)
        #pragma unroll
        for (int s = 0; s < 2; s++) {
            const float4 v = *reinterpret_cast<const float4*>(
                &A[(size_t)(m0 + arow + s * 64) * K + k0 + acol]);
            As[acol + 0][arow + s * 64] = v.x;
            As[acol + 1][arow + s * 64] = v.y;
            As[acol + 2][arow + s * 64] = v.z;
            As[acol + 3][arow + s * 64] = v.w;
        }
        // W tile: rows k0..+15, cols n0..+127
        #pragma unroll
        for (int s = 0; s < 2; s++) {
            const float4 v = *reinterpret_cast<const float4*>(
                &W[(size_t)(k0 + wrow + s * 8) * N + n0 + wcol]);
            *reinterpret_cast<float4*>(&Ws[wrow + s * 8][wcol]) = v;
        }
        __syncthreads();

        #pragma unroll
        for (int k = 0; k < GBK; k++) {
            float a[8], b[8];
            #pragma unroll
            for (int i = 0; i < 8; i += 4) {
                const float4 v = *reinterpret_cast<const float4*>(&As[k][tr * 8 + i]);
                a[i+0] = v.x; a[i+1] = v.y; a[i+2] = v.z; a[i+3] = v.w;
            }
            #pragma unroll
            for (int j = 0; j < 8; j += 4) {
                const float4 v = *reinterpret_cast<const float4*>(&Ws[k][tc * 8 + j]);
                b[j+0] = v.x; b[j+1] = v.y; b[j+2] = v.z; b[j+3] = v.w;
            }
            #pragma unroll
            for (int i = 0; i < 8; i++)
                #pragma unroll
                for (int j = 0; j < 8; j++)
                    acc[i][j] = fmaf(a[i], b[j], acc[i][j]);
        }
        __syncthreads();
    }

    // epilogue: add bias, vectorized store
    #pragma unroll
    for (int i = 0; i < 8; i++) {
        const int m = m0 + tr * 8 + i;
        #pragma unroll
        for (int j = 0; j < 8; j += 4) {
            const int n = n0 + tc * 8 + j;
            float4 v;
            v.x = acc[i][j+0] + bias[n+0];
            v.y = acc[i][j+1] + bias[n+1];
            v.z = acc[i][j+2] + bias[n+2];
            v.w = acc[i][j+3] + bias[n+3];
            *reinterpret_cast<float4*>(&Cout[(size_t)m * N + n]) = v;
        }
    }
}

// ---------------- Flash attention (causal), fp32 ----------------
// grid: (T/BQ, NH, B), 256 threads. BQ=64 query rows, BKV=32 key rows per tile.
#define BQ  64
#define BKV 32

__global__ __launch_bounds__(256, 2)
void flash_attn_kernel(const float* __restrict__ qkv, float* __restrict__ y)
{
    __shared__ float Qs[BQ][HD + 1];    // stride 65
    __shared__ float Ks[BKV][HD + 1];
    __shared__ float Vs[BKV][HD + 1];
    __shared__ float Ps[BQ][BKV + 1];   // stride 33

    const int tid = threadIdx.x;
    const int ty  = tid / 16;           // 0..15 -> rows ty*4..+3
    const int tx  = tid % 16;           // 0..15 -> S cols tx*2..+1 ; O cols tx+16j
    const int q0  = blockIdx.x * BQ;
    const int h   = blockIdx.y;
    const int b   = blockIdx.z;

    const float* base = qkv + (size_t)b * TT * C3 + h * HD;

    // Load Q tile (pre-scaled by 1/sqrt(HD) = 0.125)
    for (int e = tid; e < BQ * HD; e += 256) {
        const int r = e >> 6, d = e & 63;
        Qs[r][d] = base[(size_t)(q0 + r) * C3 + d] * 0.125f;
    }

    float m_i[4], l_i[4], O[4][4];
    #pragma unroll
    for (int i = 0; i < 4; i++) {
        m_i[i] = -1e30f; l_i[i] = 0.f;
        #pragma unroll
        for (int j = 0; j < 4; j++) O[i][j] = 0.f;
    }

    const int kend = q0 + BQ;   // causal: keys 0 .. q0+BQ-1
    for (int kt = 0; kt < kend; kt += BKV) {
        __syncthreads();   // protect Ks/Vs/Ps from previous iteration readers (also covers Qs at kt=0)
        for (int e = tid; e < BKV * HD; e += 256) {
            const int r = e >> 6, d = e & 63;
            const float* rowp = base + (size_t)(kt + r) * C3;
            Ks[r][d] = rowp[CC  + d];
            Vs[r][d] = rowp[2*CC + d];
        }
        __syncthreads();

        // S = Q K^T for this thread's 4 rows x 2 cols
        float s[4][2] = {{0.f,0.f},{0.f,0.f},{0.f,0.f},{0.f,0.f}};
        #pragma unroll 8
        for (int d = 0; d < HD; d++) {
            const float k0v = Ks[tx*2 + 0][d];
            const float k1v = Ks[tx*2 + 1][d];
            #pragma unroll
            for (int i = 0; i < 4; i++) {
                const float qv = Qs[ty*4 + i][d];
                s[i][0] = fmaf(qv, k0v, s[i][0]);
                s[i][1] = fmaf(qv, k1v, s[i][1]);
            }
        }
        // causal mask
        #pragma unroll
        for (int i = 0; i < 4; i++) {
            const int qg = q0 + ty*4 + i;
            #pragma unroll
            for (int j = 0; j < 2; j++)
                if (kt + tx*2 + j > qg) s[i][j] = -1e30f;
        }
        // online softmax update (reduce across the 16 tx lanes; xor<16 stays in half-warp)
        #pragma unroll
        for (int i = 0; i < 4; i++) {
            float mx = fmaxf(s[i][0], s[i][1]);
            #pragma unroll
            for (int off = 8; off >= 1; off >>= 1)
                mx = fmaxf(mx, __shfl_xor_sync(0xffffffffu, mx, off));
            const float mnew = fmaxf(m_i[i], mx);
            const float p0 = __expf(s[i][0] - mnew);
            const float p1 = __expf(s[i][1] - mnew);
            float rs = p0 + p1;
            #pragma unroll
            for (int off = 8; off >= 1; off >>= 1)
                rs += __shfl_xor_sync(0xffffffffu, rs, off);
            const float corr = __expf(m_i[i] - mnew);
            l_i[i] = l_i[i] * corr + rs;
            m_i[i] = mnew;
            #pragma unroll
            for (int j = 0; j < 4; j++) O[i][j] *= corr;
            Ps[ty*4 + i][tx*2 + 0] = p0;
            Ps[ty*4 + i][tx*2 + 1] = p1;
        }
        __syncthreads();

        // O += P @ V   (O cols d = tx + 16j  -> conflict-free, coalesced epilogue)
        #pragma unroll 4
        for (int c = 0; c < BKV; c++) {
            float v[4];
            #pragma unroll
            for (int j = 0; j < 4; j++) v[j] = Vs[c][tx + 16*j];
            #pragma unroll
            for (int i = 0; i < 4; i++) {
                const float p = Ps[ty*4 + i][c];
                #pragma unroll
                for (int j = 0; j < 4; j++) O[i][j] = fmaf(p, v[j], O[i][j]);
            }
        }
    }

    // write y[b, q0+r, h*HD + d]
    #pragma unroll
    for (int i = 0; i < 4; i++) {
        const float inv = 1.f / l_i[i];
        const size_t row = (size_t)b * TT + q0 + ty*4 + i;
        #pragma unroll
        for (int j = 0; j < 4; j++)
            y[row * CC + h * HD + tx + 16*j] = O[i][j] * inv;
    }
}

// ---------------- launch ----------------
extern "C" void kernel_launch(void* const* d_in, const int* in_sizes, int n_in,
                              void* d_out, int out_size)
{
    const float* x      = (const float*)d_in[0];  // [B,T,C]
    const float* W_attn = (const float*)d_in[1];  // [C,3C]
    const float* b_attn = (const float*)d_in[2];  // [3C]
    const float* W_proj = (const float*)d_in[3];  // [C,C]
    const float* b_proj = (const float*)d_in[4];  // [C]
    float* out = (float*)d_out;                   // [B,T,C]

    float* qkv = nullptr; float* y = nullptr;
    cudaGetSymbolAddress((void**)&qkv, g_qkv);
    cudaGetSymbolAddress((void**)&y,   g_y);

    const int M = BB * TT;   // 8192

    // 1) qkv = x @ W_attn + b_attn   [8192 x 2304]
    {
        dim3 grid(C3 / GBN, M / GBM);   // (18, 64)
        sgemm_bias_kernel<<<grid, 256>>>(x, W_attn, b_attn, qkv, M, C3, CC);
    }
    // 2) flash attention -> y [8192 x 768]
    {
        dim3 grid(TT / BQ, NH, BB);     // (16, 12, 8)
        flash_attn_kernel<<<grid, 256>>>(qkv, y);
    }
    // 3) out = y @ W_proj + b_proj   [8192 x 768]
    {
        dim3 grid(CC / GBN, M / GBM);   // (6, 64)
        sgemm_bias_kernel<<<grid, 256>>>(y, W_proj, b_proj, out, M, CC, CC);
    }
}

// round 2
// speedup vs baseline: 1.5877x; 1.5877x over previous
#include <cuda_runtime.h>
#include <cuda_bf16.h>
#include <math.h>

// Problem constants
#define BB 8
#define TT 1024
#define CC 768
#define NH 12
#define HD 64
#define C3 (3*CC)   // 2304

// ---------------- scratch (no allocation allowed) ----------------
__device__ float g_qkv[BB * TT * C3];   // [B,T,3C]  75.5 MB
__device__ float g_y  [BB * TT * CC];   // [B,T,C]   25 MB

// ================= tf32 tensor-core GEMM =================
// C[M,N] = A[M,K] @ W[K,N] + bias[N]
// BM=128, BN=128, BK=16, 256 threads (8 warps, 2x4), warp tile 64x32,
// mma.m16n8k8.tf32 with fp32 accumulate, cp.async double buffering.
#define BM 128
#define BN 128
#define BK 16
#define AS_STRIDE (BK + 4)     // 20 floats: frag loads hit all 32 banks
#define BS_STRIDE (BN + 8)     // 136 floats: frag loads hit all 32 banks

__device__ __forceinline__ unsigned f2tf(float x) {
    unsigned r;
    asm("cvt.rna.tf32.f32 %0, %1;" : "=r"(r) : "f"(x));
    return r;
}

__device__ __forceinline__ void cp_async16(void* smem, const void* gmem) {
    unsigned s = (unsigned)__cvta_generic_to_shared(smem);
    asm volatile("cp.async.cg.shared.global [%0], [%1], 16;\n" :: "r"(s), "l"(gmem));
}

__global__ __launch_bounds__(256, 2)
void tf32_gemm_bias(const float* __restrict__ A,
                    const float* __restrict__ W,
                    const float* __restrict__ bias,
                    float* __restrict__ Cout,
                    int M, int N, int K)
{
    __shared__ float As[2][BM][AS_STRIDE];
    __shared__ float Bs[2][BK][BS_STRIDE];

    const int tid  = threadIdx.x;
    const int lane = tid & 31;
    const int warp = tid >> 5;
    const int wm   = warp >> 2;          // 0..1
    const int wn   = warp & 3;           // 0..3
    const int grp  = lane >> 2;          // 0..7
    const int qd   = lane & 3;           // 0..3
    const int m0   = blockIdx.y * BM;
    const int n0   = blockIdx.x * BN;

    // cp.async mapping
    const int a_row = tid >> 2;          // 0..63 (+64 for 2nd chunk)
    const int a_col = (tid & 3) * 4;     // 0,4,8,12
    const int b_row = tid >> 5;          // 0..7 (+8 for 2nd chunk)
    const int b_col = (tid & 31) * 4;    // 0..124

    float acc[4][4][4] = {};             // [mt][nt][4]

    auto load_tile = [&](int buf, int k0) {
        cp_async16(&As[buf][a_row     ][a_col], &A[(size_t)(m0 + a_row     ) * K + k0 + a_col]);
        cp_async16(&As[buf][a_row + 64][a_col], &A[(size_t)(m0 + a_row + 64) * K + k0 + a_col]);
        cp_async16(&Bs[buf][b_row    ][b_col], &W[(size_t)(k0 + b_row    ) * N + n0 + b_col]);
        cp_async16(&Bs[buf][b_row + 8][b_col], &W[(size_t)(k0 + b_row + 8) * N + n0 + b_col]);
        asm volatile("cp.async.commit_group;\n");
    };

    const int nk = K / BK;
    load_tile(0, 0);
    asm volatile("cp.async.wait_group 0;\n");
    __syncthreads();

    for (int t = 0; t < nk; t++) {
        const int buf = t & 1;
        if (t + 1 < nk) load_tile(buf ^ 1, (t + 1) * BK);

        #pragma unroll
        for (int ks = 0; ks < BK; ks += 8) {
            unsigned afr[4][4], bfr[4][2];
            #pragma unroll
            for (int mt = 0; mt < 4; mt++) {
                const int rb = wm * 64 + mt * 16;
                afr[mt][0] = f2tf(As[buf][rb + grp    ][ks + qd    ]);
                afr[mt][1] = f2tf(As[buf][rb + grp + 8][ks + qd    ]);
                afr[mt][2] = f2tf(As[buf][rb + grp    ][ks + qd + 4]);
                afr[mt][3] = f2tf(As[buf][rb + grp + 8][ks + qd + 4]);
            }
            #pragma unroll
            for (int nt = 0; nt < 4; nt++) {
                const int cb = wn * 32 + nt * 8 + grp;
                bfr[nt][0] = f2tf(Bs[buf][ks + qd    ][cb]);
                bfr[nt][1] = f2tf(Bs[buf][ks + qd + 4][cb]);
            }
            #pragma unroll
            for (int mt = 0; mt < 4; mt++)
                #pragma unroll
                for (int nt = 0; nt < 4; nt++) {
                    asm volatile(
                        "mma.sync.aligned.m16n8k8.row.col.f32.tf32.tf32.f32 "
                        "{%0,%1,%2,%3}, {%4,%5,%6,%7}, {%8,%9}, {%0,%1,%2,%3};"
                        : "+f"(acc[mt][nt][0]), "+f"(acc[mt][nt][1]),
                          "+f"(acc[mt][nt][2]), "+f"(acc[mt][nt][3])
                        : "r"(afr[mt][0]), "r"(afr[mt][1]), "r"(afr[mt][2]), "r"(afr[mt][3]),
                          "r"(bfr[nt][0]), "r"(bfr[nt][1]));
                }
        }

        if (t + 1 < nk) asm volatile("cp.async.wait_group 0;\n");
        __syncthreads();
    }

    // epilogue: bias + store (float2 per fragment row)
    #pragma unroll
    for (int mt = 0; mt < 4; mt++) {
        const int r = m0 + wm * 64 + mt * 16 + grp;
        #pragma unroll
        for (int nt = 0; nt < 4; nt++) {
            const int c = n0 + wn * 32 + nt * 8 + qd * 2;
            const float2 bi = *reinterpret_cast<const float2*>(&bias[c]);
            float2 v0, v1;
            v0.x = acc[mt][nt][0] + bi.x;  v0.y = acc[mt][nt][1] + bi.y;
            v1.x = acc[mt][nt][2] + bi.x;  v1.y = acc[mt][nt][3] + bi.y;
            *reinterpret_cast<float2*>(&Cout[(size_t)r       * N + c]) = v0;
            *reinterpret_cast<float2*>(&Cout[(size_t)(r + 8) * N + c]) = v1;
        }
    }
}

// ---------------- Flash attention (causal), fp32 ----------------
// grid: (T/BQ, NH, B), 256 threads. BQ=64 query rows, BKV=32 key rows per tile.
#define BQ  64
#define BKV 32

__global__ __launch_bounds__(256, 2)
void flash_attn_kernel(const float* __restrict__ qkv, float* __restrict__ y)
{
    __shared__ float Qs[BQ][HD + 1];    // stride 65
    __shared__ float Ks[BKV][HD + 1];
    __shared__ float Vs[BKV][HD + 1];
    __shared__ float Ps[BQ][BKV + 1];   // stride 33

    const int tid = threadIdx.x;
    const int ty  = tid / 16;           // 0..15 -> rows ty*4..+3
    const int tx  = tid % 16;           // 0..15 -> S cols tx*2..+1 ; O cols tx+16j
    const int q0  = blockIdx.x * BQ;
    const int h   = blockIdx.y;
    const int b   = blockIdx.z;

    const float* base = qkv + (size_t)b * TT * C3 + h * HD;

    // Load Q tile (pre-scaled by 1/sqrt(HD) = 0.125)
    for (int e = tid; e < BQ * HD; e += 256) {
        const int r = e >> 6, d = e & 63;
        Qs[r][d] = base[(size_t)(q0 + r) * C3 + d] * 0.125f;
    }

    float m_i[4], l_i[4], O[4][4];
    #pragma unroll
    for (int i = 0; i < 4; i++) {
        m_i[i] = -1e30f; l_i[i] = 0.f;
        #pragma unroll
        for (int j = 0; j < 4; j++) O[i][j] = 0.f;
    }

    const int kend = q0 + BQ;   // causal: keys 0 .. q0+BQ-1
    for (int kt = 0; kt < kend; kt += BKV) {
        __syncthreads();   // protect Ks/Vs/Ps from previous iteration readers (also covers Qs at kt=0)
        for (int e = tid; e < BKV * HD; e += 256) {
            const int r = e >> 6, d = e & 63;
            const float* rowp = base + (size_t)(kt + r) * C3;
            Ks[r][d] = rowp[CC  + d];
            Vs[r][d] = rowp[2*CC + d];
        }
        __syncthreads();

        // S = Q K^T for this thread's 4 rows x 2 cols
        float s[4][2] = {{0.f,0.f},{0.f,0.f},{0.f,0.f},{0.f,0.f}};
        #pragma unroll 8
        for (int d = 0; d < HD; d++) {
            const float k0v = Ks[tx*2 + 0][d];
            const float k1v = Ks[tx*2 + 1][d];
            #pragma unroll
            for (int i = 0; i < 4; i++) {
                const float qv = Qs[ty*4 + i][d];
                s[i][0] = fmaf(qv, k0v, s[i][0]);
                s[i][1] = fmaf(qv, k1v, s[i][1]);
            }
        }
        // causal mask
        #pragma unroll
        for (int i = 0; i < 4; i++) {
            const int qg = q0 + ty*4 + i;
            #pragma unroll
            for (int j = 0; j < 2; j++)
                if (kt + tx*2 + j > qg) s[i][j] = -1e30f;
        }
        // online softmax update (reduce across the 16 tx lanes; xor<16 stays in half-warp)
        #pragma unroll
        for (int i = 0; i < 4; i++) {
            float mx = fmaxf(s[i][0], s[i][1]);
            #pragma unroll
            for (int off = 8; off >= 1; off >>= 1)
                mx = fmaxf(mx, __shfl_xor_sync(0xffffffffu, mx, off));
            const float mnew = fmaxf(m_i[i], mx);
            const float p0 = __expf(s[i][0] - mnew);
            const float p1 = __expf(s[i][1] - mnew);
            float rs = p0 + p1;
            #pragma unroll
            for (int off = 8; off >= 1; off >>= 1)
                rs += __shfl_xor_sync(0xffffffffu, rs, off);
            const float corr = __expf(m_i[i] - mnew);
            l_i[i] = l_i[i] * corr + rs;
            m_i[i] = mnew;
            #pragma unroll
            for (int j = 0; j < 4; j++) O[i][j] *= corr;
            Ps[ty*4 + i][tx*2 + 0] = p0;
            Ps[ty*4 + i][tx*2 + 1] = p1;
        }
        __syncthreads();

        // O += P @ V   (O cols d = tx + 16j  -> conflict-free, coalesced epilogue)
        #pragma unroll 4
        for (int c = 0; c < BKV; c++) {
            float v[4];
            #pragma unroll
            for (int j = 0; j < 4; j++) v[j] = Vs[c][tx + 16*j];
            #pragma unroll
            for (int i = 0; i < 4; i++) {
                const float p = Ps[ty*4 + i][c];
                #pragma unroll
                for (int j = 0; j < 4; j++) O[i][j] = fmaf(p, v[j], O[i][j]);
            }
        }
    }

    // write y[b, q0+r, h*HD + d]
    #pragma unroll
    for (int i = 0; i < 4; i++) {
        const float inv = 1.f / l_i[i];
        const size_t row = (size_t)b * TT + q0 + ty*4 + i;
        #pragma unroll
        for (int j = 0; j < 4; j++)
            y[row * CC + h * HD + tx + 16*j] = O[i][j] * inv;
    }
}

// ---------------- launch ----------------
extern "C" void kernel_launch(void* const* d_in, const int* in_sizes, int n_in,
                              void* d_out, int out_size)
{
    const float* x      = (const float*)d_in[0];  // [B,T,C]
    const float* W_attn = (const float*)d_in[1];  // [C,3C]
    const float* b_attn = (const float*)d_in[2];  // [3C]
    const float* W_proj = (const float*)d_in[3];  // [C,C]
    const float* b_proj = (const float*)d_in[4];  // [C]
    float* out = (float*)d_out;                   // [B,T,C]

    float* qkv = nullptr; float* y = nullptr;
    cudaGetSymbolAddress((void**)&qkv, g_qkv);
    cudaGetSymbolAddress((void**)&y,   g_y);

    const int M = BB * TT;   // 8192

    // 1) qkv = x @ W_attn + b_attn   [8192 x 2304]
    {
        dim3 grid(C3 / BN, M / BM);     // (18, 64)
        tf32_gemm_bias<<<grid, 256>>>(x, W_attn, b_attn, qkv, M, C3, CC);
    }
    // 2) flash attention -> y [8192 x 768]
    {
        dim3 grid(TT / BQ, NH, BB);     // (16, 12, 8)
        flash_attn_kernel<<<grid, 256>>>(qkv, y);
    }
    // 3) out = y @ W_proj + b_proj   [8192 x 768]
    {
        dim3 grid(CC / BN, M / BM);     // (6, 64)
        tf32_gemm_bias<<<grid, 256>>>(y, W_proj, b_proj, out, M, CC, CC);
    }
}

// round 3
// speedup vs baseline: 2.9066x; 1.8307x over previous
#include <cuda_runtime.h>
#include <cuda_bf16.h>
#include <math.h>

// Problem constants
#define BB 8
#define TT 1024
#define CC 768
#define NH 12
#define HD 64
#define C3 (3*CC)   // 2304

// ---------------- scratch (no allocation allowed) ----------------
__device__ float g_qkv[BB * TT * C3];   // [B,T,3C]  75.5 MB
__device__ float g_y  [BB * TT * CC];   // [B,T,C]   25 MB

__device__ __forceinline__ unsigned f2tf(float x) {
    unsigned r;
    asm("cvt.rna.tf32.f32 %0, %1;" : "=r"(r) : "f"(x));
    return r;
}

__device__ __forceinline__ void cp_async16(void* smem, const void* gmem) {
    unsigned s = (unsigned)__cvta_generic_to_shared(smem);
    asm volatile("cp.async.cg.shared.global [%0], [%1], 16;\n" :: "r"(s), "l"(gmem));
}

#define MMA_TF32(acc, a, b0v, b1v)                                              \
    asm volatile(                                                               \
        "mma.sync.aligned.m16n8k8.row.col.f32.tf32.tf32.f32 "                   \
        "{%0,%1,%2,%3}, {%4,%5,%6,%7}, {%8,%9}, {%0,%1,%2,%3};"                 \
        : "+f"(acc[0]), "+f"(acc[1]), "+f"(acc[2]), "+f"(acc[3])                \
        : "r"(a[0]), "r"(a[1]), "r"(a[2]), "r"(a[3]), "r"(b0v), "r"(b1v))

// ================= tf32 tensor-core GEMM =================
#define BM 128
#define BN 128
#define BK 16
#define AS_STRIDE (BK + 4)
#define BS_STRIDE (BN + 8)

__global__ __launch_bounds__(256, 2)
void tf32_gemm_bias(const float* __restrict__ A,
                    const float* __restrict__ W,
                    const float* __restrict__ bias,
                    float* __restrict__ Cout,
                    int M, int N, int K)
{
    __shared__ float As[2][BM][AS_STRIDE];
    __shared__ float Bs[2][BK][BS_STRIDE];

    const int tid  = threadIdx.x;
    const int lane = tid & 31;
    const int warp = tid >> 5;
    const int wm   = warp >> 2;
    const int wn   = warp & 3;
    const int grp  = lane >> 2;
    const int qd   = lane & 3;
    const int m0   = blockIdx.y * BM;
    const int n0   = blockIdx.x * BN;

    const int a_row = tid >> 2;
    const int a_col = (tid & 3) * 4;
    const int b_row = tid >> 5;
    const int b_col = (tid & 31) * 4;

    float acc[4][4][4] = {};

    auto load_tile = [&](int buf, int k0) {
        cp_async16(&As[buf][a_row     ][a_col], &A[(size_t)(m0 + a_row     ) * K + k0 + a_col]);
        cp_async16(&As[buf][a_row + 64][a_col], &A[(size_t)(m0 + a_row + 64) * K + k0 + a_col]);
        cp_async16(&Bs[buf][b_row    ][b_col], &W[(size_t)(k0 + b_row    ) * N + n0 + b_col]);
        cp_async16(&Bs[buf][b_row + 8][b_col], &W[(size_t)(k0 + b_row + 8) * N + n0 + b_col]);
        asm volatile("cp.async.commit_group;\n");
    };

    const int nk = K / BK;
    load_tile(0, 0);
    asm volatile("cp.async.wait_group 0;\n");
    __syncthreads();

    for (int t = 0; t < nk; t++) {
        const int buf = t & 1;
        if (t + 1 < nk) load_tile(buf ^ 1, (t + 1) * BK);

        #pragma unroll
        for (int ks = 0; ks < BK; ks += 8) {
            unsigned afr[4][4], bfr[4][2];
            #pragma unroll
            for (int mt = 0; mt < 4; mt++) {
                const int rb = wm * 64 + mt * 16;
                afr[mt][0] = f2tf(As[buf][rb + grp    ][ks + qd    ]);
                afr[mt][1] = f2tf(As[buf][rb + grp + 8][ks + qd    ]);
                afr[mt][2] = f2tf(As[buf][rb + grp    ][ks + qd + 4]);
                afr[mt][3] = f2tf(As[buf][rb + grp + 8][ks + qd + 4]);
            }
            #pragma unroll
            for (int nt = 0; nt < 4; nt++) {
                const int cb = wn * 32 + nt * 8 + grp;
                bfr[nt][0] = f2tf(Bs[buf][ks + qd    ][cb]);
                bfr[nt][1] = f2tf(Bs[buf][ks + qd + 4][cb]);
            }
            #pragma unroll
            for (int mt = 0; mt < 4; mt++)
                #pragma unroll
                for (int nt = 0; nt < 4; nt++)
                    MMA_TF32(acc[mt][nt], afr[mt], bfr[nt][0], bfr[nt][1]);
        }

        if (t + 1 < nk) asm volatile("cp.async.wait_group 0;\n");
        __syncthreads();
    }

    #pragma unroll
    for (int mt = 0; mt < 4; mt++) {
        const int r = m0 + wm * 64 + mt * 16 + grp;
        #pragma unroll
        for (int nt = 0; nt < 4; nt++) {
            const int c = n0 + wn * 32 + nt * 8 + qd * 2;
            const float2 bi = *reinterpret_cast<const float2*>(&bias[c]);
            float2 v0, v1;
            v0.x = acc[mt][nt][0] + bi.x;  v0.y = acc[mt][nt][1] + bi.y;
            v1.x = acc[mt][nt][2] + bi.x;  v1.y = acc[mt][nt][3] + bi.y;
            *reinterpret_cast<float2*>(&Cout[(size_t)r       * N + c]) = v0;
            *reinterpret_cast<float2*>(&Cout[(size_t)(r + 8) * N + c]) = v1;
        }
    }
}

// ================= tf32 tensor-core flash attention (causal) =================
// grid (TT/128, NH, BB), 256 threads (8 warps, 16 query rows each), BKV=64.
#define FBQ  128
#define FBKV 64
#define KS_STR 68   // ≡4 mod 32: conflict-free for (grp-row, qd-col) b-frag reads
#define VS_STR 72   // ≡8 mod 32: conflict-free for (qd-row, grp-col) b-frag reads
#define PS_STR 68

// dynamic smem layout (floats)
#define OFF_K 0
#define OFF_V (2 * FBKV * KS_STR)                 // 8704
#define OFF_P (OFF_V + 2 * FBKV * VS_STR)         // 17920
#define FLASH_SMEM_FLOATS (OFF_P + FBQ * PS_STR)  // 26624
#define FLASH_SMEM_BYTES (FLASH_SMEM_FLOATS * 4)  // 106496

__global__ __launch_bounds__(256)
void flash_attn_tf32(const float* __restrict__ qkv, float* __restrict__ y)
{
    extern __shared__ float fsm[];
    float* KsBase = fsm + OFF_K;   // [2][FBKV][KS_STR]
    float* VsBase = fsm + OFF_V;   // [2][FBKV][VS_STR]
    float* Psm    = fsm + OFF_P;   // [FBQ][PS_STR]

    const int tid  = threadIdx.x;
    const int lane = tid & 31;
    const int warp = tid >> 5;
    const int grp  = lane >> 2;    // 0..7
    const int qd   = lane & 3;     // 0..3
    const int q0   = blockIdx.x * FBQ;
    const int h    = blockIdx.y;
    const int b    = blockIdx.z;
    const int wb   = warp * 16;    // warp's query-row base within block

    const float* base = qkv + (size_t)b * TT * C3 + h * HD;

    // ---- stage Q (scaled) into this warp's Ps rows, build tf32 A-fragments ----
    {
        const int r0 = (lane >> 4);        // 0..1
        const int c  = (lane & 15) * 4;    // 0..60
        #pragma unroll
        for (int p = 0; p < 8; p++) {
            const int r = p * 2 + r0;
            const float4 v = *reinterpret_cast<const float4*>(
                &base[(size_t)(q0 + wb + r) * C3 + c]);
            float* d = &Psm[(wb + r) * PS_STR + c];
            d[0] = v.x * 0.125f; d[1] = v.y * 0.125f;
            d[2] = v.z * 0.125f; d[3] = v.w * 0.125f;
        }
    }
    __syncwarp();
    unsigned qfr[8][4];
    #pragma unroll
    for (int ks = 0; ks < 8; ks++) {
        qfr[ks][0] = f2tf(Psm[(wb + grp    ) * PS_STR + ks * 8 + qd    ]);
        qfr[ks][1] = f2tf(Psm[(wb + grp + 8) * PS_STR + ks * 8 + qd    ]);
        qfr[ks][2] = f2tf(Psm[(wb + grp    ) * PS_STR + ks * 8 + qd + 4]);
        qfr[ks][3] = f2tf(Psm[(wb + grp + 8) * PS_STR + ks * 8 + qd + 4]);
    }

    auto load_kv = [&](int bf, int kt) {
        const int r = tid >> 4;            // 0..15
        const int c = (tid & 15) * 4;      // 0..60
        float* Kd = KsBase + bf * (FBKV * KS_STR);
        float* Vd = VsBase + bf * (FBKV * VS_STR);
        #pragma unroll
        for (int p = 0; p < 4; p++) {
            const float* rowp = base + (size_t)(kt + r + p * 16) * C3;
            cp_async16(&Kd[(r + p * 16) * KS_STR + c], rowp + CC  + c);
            cp_async16(&Vd[(r + p * 16) * VS_STR + c], rowp + 2*CC + c);
        }
        asm volatile("cp.async.commit_group;\n");
    };

    float m_i[2] = {-1e30f, -1e30f};
    float l_i[2] = {0.f, 0.f};
    float O[8][4] = {};

    const int ntiles = (q0 + FBQ) / FBKV;
    load_kv(0, 0);

    for (int t = 0; t < ntiles; t++) {
        const int buf = t & 1;
        const int kt  = t * FBKV;
        asm volatile("cp.async.wait_group 0;\n");
        __syncthreads();
        if (t + 1 < ntiles) load_kv(buf ^ 1, kt + FBKV);

        const float* Kb = KsBase + buf * (FBKV * KS_STR);
        const float* Vb = VsBase + buf * (FBKV * VS_STR);

        // ---- S = Q @ K^T  (warp: 16 x 64) ----
        float sc[8][4] = {};
        #pragma unroll
        for (int ks = 0; ks < 8; ks++) {
            #pragma unroll
            for (int nt = 0; nt < 8; nt++) {
                const unsigned b0 = f2tf(Kb[(nt * 8 + grp) * KS_STR + ks * 8 + qd    ]);
                const unsigned b1 = f2tf(Kb[(nt * 8 + grp) * KS_STR + ks * 8 + qd + 4]);
                MMA_TF32(sc[nt], qfr[ks], b0, b1);
            }
        }

        // ---- causal mask (only diagonal tiles) ----
        if (kt + FBKV > q0) {
            const int r0g = q0 + wb + grp;
            const int r1g = r0g + 8;
            #pragma unroll
            for (int nt = 0; nt < 8; nt++) {
                const int c0 = kt + nt * 8 + 2 * qd;
                if (c0     > r0g) sc[nt][0] = -1e30f;
                if (c0 + 1 > r0g) sc[nt][1] = -1e30f;
                if (c0     > r1g) sc[nt][2] = -1e30f;
                if (c0 + 1 > r1g) sc[nt][3] = -1e30f;
            }
        }

        // ---- online softmax ----
        float mx0 = -1e30f, mx1 = -1e30f;
        #pragma unroll
        for (int nt = 0; nt < 8; nt++) {
            mx0 = fmaxf(mx0, fmaxf(sc[nt][0], sc[nt][1]));
            mx1 = fmaxf(mx1, fmaxf(sc[nt][2], sc[nt][3]));
        }
        #pragma unroll
        for (int off = 1; off <= 2; off <<= 1) {
            mx0 = fmaxf(mx0, __shfl_xor_sync(0xffffffffu, mx0, off));
            mx1 = fmaxf(mx1, __shfl_xor_sync(0xffffffffu, mx1, off));
        }
        const float mn0 = fmaxf(m_i[0], mx0);
        const float mn1 = fmaxf(m_i[1], mx1);
        const float cr0 = __expf(m_i[0] - mn0);
        const float cr1 = __expf(m_i[1] - mn1);
        m_i[0] = mn0; m_i[1] = mn1;

        float rs0 = 0.f, rs1 = 0.f;
        #pragma unroll
        for (int nt = 0; nt < 8; nt++) {
            sc[nt][0] = __expf(sc[nt][0] - mn0);
            sc[nt][1] = __expf(sc[nt][1] - mn0);
            sc[nt][2] = __expf(sc[nt][2] - mn1);
            sc[nt][3] = __expf(sc[nt][3] - mn1);
            rs0 += sc[nt][0] + sc[nt][1];
            rs1 += sc[nt][2] + sc[nt][3];
        }
        #pragma unroll
        for (int off = 1; off <= 2; off <<= 1) {
            rs0 += __shfl_xor_sync(0xffffffffu, rs0, off);
            rs1 += __shfl_xor_sync(0xffffffffu, rs1, off);
        }
        l_i[0] = l_i[0] * cr0 + rs0;
        l_i[1] = l_i[1] * cr1 + rs1;
        #pragma unroll
        for (int nt = 0; nt < 8; nt++) {
            O[nt][0] *= cr0; O[nt][1] *= cr0;
            O[nt][2] *= cr1; O[nt][3] *= cr1;
        }

        // ---- stage P (per-warp region; cross-lane => syncwarp) ----
        __syncwarp();
        #pragma unroll
        for (int nt = 0; nt < 8; nt++) {
            *reinterpret_cast<float2*>(&Psm[(wb + grp    ) * PS_STR + nt * 8 + 2 * qd]) =
                make_float2(sc[nt][0], sc[nt][1]);
            *reinterpret_cast<float2*>(&Psm[(wb + grp + 8) * PS_STR + nt * 8 + 2 * qd]) =
                make_float2(sc[nt][2], sc[nt][3]);
        }
        __syncwarp();

        // ---- O += P @ V ----
        #pragma unroll
        for (int ks = 0; ks < 8; ks++) {
            unsigned afr[4];
            afr[0] = f2tf(Psm[(wb + grp    ) * PS_STR + ks * 8 + qd    ]);
            afr[1] = f2tf(Psm[(wb + grp + 8) * PS_STR + ks * 8 + qd    ]);
            afr[2] = f2tf(Psm[(wb + grp    ) * PS_STR + ks * 8 + qd + 4]);
            afr[3] = f2tf(Psm[(wb + grp + 8) * PS_STR + ks * 8 + qd + 4]);
            #pragma unroll
            for (int nt = 0; nt < 8; nt++) {
                const unsigned b0 = f2tf(Vb[(ks * 8 + qd    ) * VS_STR + nt * 8 + grp]);
                const unsigned b1 = f2tf(Vb[(ks * 8 + qd + 4) * VS_STR + nt * 8 + grp]);
                MMA_TF32(O[nt], afr, b0, b1);
            }
        }
    }

    // ---- epilogue: y[b, row, h*HD + col] = O / l ----
    const float inv0 = 1.f / l_i[0];
    const float inv1 = 1.f / l_i[1];
    const size_t r0 = (size_t)b * TT + q0 + wb + grp;
    const size_t r1 = r0 + 8;
    #pragma unroll
    for (int nt = 0; nt < 8; nt++) {
        const int c = h * HD + nt * 8 + 2 * qd;
        *reinterpret_cast<float2*>(&y[r0 * CC + c]) =
            make_float2(O[nt][0] * inv0, O[nt][1] * inv0);
        *reinterpret_cast<float2*>(&y[r1 * CC + c]) =
            make_float2(O[nt][2] * inv1, O[nt][3] * inv1);
    }
}

// ---------------- launch ----------------
extern "C" void kernel_launch(void* const* d_in, const int* in_sizes, int n_in,
                              void* d_out, int out_size)
{
    const float* x      = (const float*)d_in[0];  // [B,T,C]
    const float* W_attn = (const float*)d_in[1];  // [C,3C]
    const float* b_attn = (const float*)d_in[2];  // [3C]
    const float* W_proj = (const float*)d_in[3];  // [C,C]
    const float* b_proj = (const float*)d_in[4];  // [C]
    float* out = (float*)d_out;                   // [B,T,C]

    float* qkv = nullptr; float* y = nullptr;
    cudaGetSymbolAddress((void**)&qkv, g_qkv);
    cudaGetSymbolAddress((void**)&y,   g_y);

    // allow >48KB dynamic smem for the attention kernel (idempotent, capture-safe)
    cudaFuncSetAttribute(flash_attn_tf32,
                         cudaFuncAttributeMaxDynamicSharedMemorySize,
                         FLASH_SMEM_BYTES);

    const int M = BB * TT;   // 8192

    // 1) qkv = x @ W_attn + b_attn   [8192 x 2304]
    {
        dim3 grid(C3 / BN, M / BM);     // (18, 64)
        tf32_gemm_bias<<<grid, 256>>>(x, W_attn, b_attn, qkv, M, C3, CC);
    }
    // 2) flash attention -> y [8192 x 768]
    {
        dim3 grid(TT / FBQ, NH, BB);    // (8, 12, 8)
        flash_attn_tf32<<<grid, 256, FLASH_SMEM_BYTES>>>(qkv, y);
    }
    // 3) out = y @ W_proj + b_proj   [8192 x 768]
    {
        dim3 grid(CC / BN, M / BM);     // (6, 64)
        tf32_gemm_bias<<<grid, 256>>>(y, W_proj, b_proj, out, M, CC, CC);
    }
}

// round 4
// speedup vs baseline: 3.3299x; 1.1456x over previous
#include <cuda_runtime.h>
#include <cuda_bf16.h>
#include <math.h>

// Problem constants
#define BB 8
#define TT 1024
#define CC 768
#define NH 12
#define HD 64
#define C3 (3*CC)   // 2304

// ---------------- scratch (no allocation allowed) ----------------
__device__ float g_qkv[BB * TT * C3];   // [B,T,3C]  (tf32-rounded values)
__device__ float g_y  [BB * TT * CC];   // [B,T,C]   (tf32-rounded values)
__device__ float g_xr [BB * TT * CC];   // rounded x
__device__ float g_wa [CC * C3];        // rounded W_attn
__device__ float g_wp [CC * CC];        // rounded W_proj

__device__ __forceinline__ unsigned f2tf(float x) {
    unsigned r;
    asm("cvt.rna.tf32.f32 %0, %1;" : "=r"(r) : "f"(x));
    return r;
}
__device__ __forceinline__ float roundtf(float x) { return __uint_as_float(f2tf(x)); }

__device__ __forceinline__ void cp_async16(void* smem, const void* gmem) {
    unsigned s = (unsigned)__cvta_generic_to_shared(smem);
    asm volatile("cp.async.cg.shared.global [%0], [%1], 16;\n" :: "r"(s), "l"(gmem));
}

#define MMA_TF32(acc, a, b0v, b1v)                                              \
    asm volatile(                                                               \
        "mma.sync.aligned.m16n8k8.row.col.f32.tf32.tf32.f32 "                   \
        "{%0,%1,%2,%3}, {%4,%5,%6,%7}, {%8,%9}, {%0,%1,%2,%3};"                 \
        : "+f"(acc[0]), "+f"(acc[1]), "+f"(acc[2]), "+f"(acc[3])                \
        : "r"(a[0]), "r"(a[1]), "r"(a[2]), "r"(a[3]), "r"(b0v), "r"(b1v))

// ---------------- pre-pass: round to tf32-representable fp32 ----------------
__global__ __launch_bounds__(256)
void round_tf32_kernel(const float* __restrict__ in, float* __restrict__ out, int n4)
{
    const int i = blockIdx.x * blockDim.x + threadIdx.x;
    if (i >= n4) return;
    float4 v = reinterpret_cast<const float4*>(in)[i];
    v.x = roundtf(v.x); v.y = roundtf(v.y);
    v.z = roundtf(v.z); v.w = roundtf(v.w);
    reinterpret_cast<float4*>(out)[i] = v;
}

// ================= tf32 tensor-core GEMM (inputs pre-rounded) =================
#define BM 128
#define BN 128
#define BK 16
#define AS_STRIDE (BK + 4)
#define BS_STRIDE (BN + 8)

template <bool ROUND_OUT>
__global__ __launch_bounds__(256, 2)
void tf32_gemm_bias(const float* __restrict__ A,
                    const float* __restrict__ W,
                    const float* __restrict__ bias,
                    float* __restrict__ Cout,
                    int M, int N, int K)
{
    __shared__ float As[2][BM][AS_STRIDE];
    __shared__ float Bs[2][BK][BS_STRIDE];

    const int tid  = threadIdx.x;
    const int lane = tid & 31;
    const int warp = tid >> 5;
    const int wm   = warp >> 2;
    const int wn   = warp & 3;
    const int grp  = lane >> 2;
    const int qd   = lane & 3;
    const int m0   = blockIdx.y * BM;
    const int n0   = blockIdx.x * BN;

    const int a_row = tid >> 2;
    const int a_col = (tid & 3) * 4;
    const int b_row = tid >> 5;
    const int b_col = (tid & 31) * 4;

    float acc[4][4][4] = {};

    auto load_tile = [&](int buf, int k0) {
        cp_async16(&As[buf][a_row     ][a_col], &A[(size_t)(m0 + a_row     ) * K + k0 + a_col]);
        cp_async16(&As[buf][a_row + 64][a_col], &A[(size_t)(m0 + a_row + 64) * K + k0 + a_col]);
        cp_async16(&Bs[buf][b_row    ][b_col], &W[(size_t)(k0 + b_row    ) * N + n0 + b_col]);
        cp_async16(&Bs[buf][b_row + 8][b_col], &W[(size_t)(k0 + b_row + 8) * N + n0 + b_col]);
        asm volatile("cp.async.commit_group;\n");
    };

    const int nk = K / BK;
    load_tile(0, 0);
    asm volatile("cp.async.wait_group 0;\n");
    __syncthreads();

    for (int t = 0; t < nk; t++) {
        const int buf = t & 1;
        if (t + 1 < nk) load_tile(buf ^ 1, (t + 1) * BK);

        #pragma unroll
        for (int ks = 0; ks < BK; ks += 8) {
            unsigned afr[4][4], bfr[4][2];
            #pragma unroll
            for (int mt = 0; mt < 4; mt++) {
                const int rb = wm * 64 + mt * 16;
                afr[mt][0] = __float_as_uint(As[buf][rb + grp    ][ks + qd    ]);
                afr[mt][1] = __float_as_uint(As[buf][rb + grp + 8][ks + qd    ]);
                afr[mt][2] = __float_as_uint(As[buf][rb + grp    ][ks + qd + 4]);
                afr[mt][3] = __float_as_uint(As[buf][rb + grp + 8][ks + qd + 4]);
            }
            #pragma unroll
            for (int nt = 0; nt < 4; nt++) {
                const int cb = wn * 32 + nt * 8 + grp;
                bfr[nt][0] = __float_as_uint(Bs[buf][ks + qd    ][cb]);
                bfr[nt][1] = __float_as_uint(Bs[buf][ks + qd + 4][cb]);
            }
            #pragma unroll
            for (int mt = 0; mt < 4; mt++)
                #pragma unroll
                for (int nt = 0; nt < 4; nt++)
                    MMA_TF32(acc[mt][nt], afr[mt], bfr[nt][0], bfr[nt][1]);
        }

        if (t + 1 < nk) asm volatile("cp.async.wait_group 0;\n");
        __syncthreads();
    }

    #pragma unroll
    for (int mt = 0; mt < 4; mt++) {
        const int r = m0 + wm * 64 + mt * 16 + grp;
        #pragma unroll
        for (int nt = 0; nt < 4; nt++) {
            const int c = n0 + wn * 32 + nt * 8 + qd * 2;
            const float2 bi = *reinterpret_cast<const float2*>(&bias[c]);
            float2 v0, v1;
            v0.x = acc[mt][nt][0] + bi.x;  v0.y = acc[mt][nt][1] + bi.y;
            v1.x = acc[mt][nt][2] + bi.x;  v1.y = acc[mt][nt][3] + bi.y;
            if (ROUND_OUT) {
                v0.x = roundtf(v0.x); v0.y = roundtf(v0.y);
                v1.x = roundtf(v1.x); v1.y = roundtf(v1.y);
            }
            *reinterpret_cast<float2*>(&Cout[(size_t)r       * N + c]) = v0;
            *reinterpret_cast<float2*>(&Cout[(size_t)(r + 8) * N + c]) = v1;
        }
    }
}

// ================= tf32 tensor-core flash attention (causal) =================
// qkv values are tf32-pre-rounded => fragment loads are raw bit reinterprets.
#define FBQ  128
#define FBKV 64
#define KS_STR 68
#define VS_STR 72
#define PS_STR 68

#define OFF_K 0
#define OFF_V (2 * FBKV * KS_STR)
#define OFF_P (OFF_V + 2 * FBKV * VS_STR)
#define FLASH_SMEM_FLOATS (OFF_P + FBQ * PS_STR)
#define FLASH_SMEM_BYTES (FLASH_SMEM_FLOATS * 4)   // 106496

__global__ __launch_bounds__(256)
void flash_attn_tf32(const float* __restrict__ qkv, float* __restrict__ y)
{
    extern __shared__ float fsm[];
    float* KsBase = fsm + OFF_K;
    float* VsBase = fsm + OFF_V;
    float* Psm    = fsm + OFF_P;

    const int tid  = threadIdx.x;
    const int lane = tid & 31;
    const int warp = tid >> 5;
    const int grp  = lane >> 4 ? (lane >> 2) : (lane >> 2); // 0..7
    const int g8   = lane >> 2;    // 0..7
    const int qd   = lane & 3;     // 0..3
    const int q0   = blockIdx.x * FBQ;
    const int h    = blockIdx.y;
    const int b    = blockIdx.z;
    const int wb   = warp * 16;

    const float* base = qkv + (size_t)b * TT * C3 + h * HD;

    // ---- stage Q (scaled by exact 0.125; preserves tf32-ness) ----
    {
        const int r0 = (lane >> 4);
        const int c  = (lane & 15) * 4;
        #pragma unroll
        for (int p = 0; p < 8; p++) {
            const int r = p * 2 + r0;
            const float4 v = *reinterpret_cast<const float4*>(
                &base[(size_t)(q0 + wb + r) * C3 + c]);
            float* d = &Psm[(wb + r) * PS_STR + c];
            d[0] = v.x * 0.125f; d[1] = v.y * 0.125f;
            d[2] = v.z * 0.125f; d[3] = v.w * 0.125f;
        }
    }
    __syncwarp();
    unsigned qfr[8][4];
    #pragma unroll
    for (int ks = 0; ks < 8; ks++) {
        qfr[ks][0] = __float_as_uint(Psm[(wb + g8    ) * PS_STR + ks * 8 + qd    ]);
        qfr[ks][1] = __float_as_uint(Psm[(wb + g8 + 8) * PS_STR + ks * 8 + qd    ]);
        qfr[ks][2] = __float_as_uint(Psm[(wb + g8    ) * PS_STR + ks * 8 + qd + 4]);
        qfr[ks][3] = __float_as_uint(Psm[(wb + g8 + 8) * PS_STR + ks * 8 + qd + 4]);
    }

    auto load_kv = [&](int bf, int kt) {
        const int r = tid >> 4;
        const int c = (tid & 15) * 4;
        float* Kd = KsBase + bf * (FBKV * KS_STR);
        float* Vd = VsBase + bf * (FBKV * VS_STR);
        #pragma unroll
        for (int p = 0; p < 4; p++) {
            const float* rowp = base + (size_t)(kt + r + p * 16) * C3;
            cp_async16(&Kd[(r + p * 16) * KS_STR + c], rowp + CC  + c);
            cp_async16(&Vd[(r + p * 16) * VS_STR + c], rowp + 2*CC + c);
        }
        asm volatile("cp.async.commit_group;\n");
    };

    float m_i[2] = {-1e30f, -1e30f};
    float l_i[2] = {0.f, 0.f};
    float O[8][4] = {};

    const int ntiles = (q0 + FBQ) / FBKV;
    load_kv(0, 0);

    for (int t = 0; t < ntiles; t++) {
        const int buf = t & 1;
        const int kt  = t * FBKV;
        asm volatile("cp.async.wait_group 0;\n");
        __syncthreads();
        if (t + 1 < ntiles) load_kv(buf ^ 1, kt + FBKV);

        const float* Kb = KsBase + buf * (FBKV * KS_STR);
        const float* Vb = VsBase + buf * (FBKV * VS_STR);

        // ---- S = Q @ K^T ----
        float sc[8][4] = {};
        #pragma unroll
        for (int ks = 0; ks < 8; ks++) {
            #pragma unroll
            for (int nt = 0; nt < 8; nt++) {
                const unsigned b0 = __float_as_uint(Kb[(nt * 8 + g8) * KS_STR + ks * 8 + qd    ]);
                const unsigned b1 = __float_as_uint(Kb[(nt * 8 + g8) * KS_STR + ks * 8 + qd + 4]);
                MMA_TF32(sc[nt], qfr[ks], b0, b1);
            }
        }

        // ---- causal mask (diagonal tiles only) ----
        if (kt + FBKV > q0) {
            const int r0g = q0 + wb + g8;
            const int r1g = r0g + 8;
            #pragma unroll
            for (int nt = 0; nt < 8; nt++) {
                const int c0 = kt + nt * 8 + 2 * qd;
                if (c0     > r0g) sc[nt][0] = -1e30f;
                if (c0 + 1 > r0g) sc[nt][1] = -1e30f;
                if (c0     > r1g) sc[nt][2] = -1e30f;
                if (c0 + 1 > r1g) sc[nt][3] = -1e30f;
            }
        }

        // ---- online softmax ----
        float mx0 = -1e30f, mx1 = -1e30f;
        #pragma unroll
        for (int nt = 0; nt < 8; nt++) {
            mx0 = fmaxf(mx0, fmaxf(sc[nt][0], sc[nt][1]));
            mx1 = fmaxf(mx1, fmaxf(sc[nt][2], sc[nt][3]));
        }
        #pragma unroll
        for (int off = 1; off <= 2; off <<= 1) {
            mx0 = fmaxf(mx0, __shfl_xor_sync(0xffffffffu, mx0, off));
            mx1 = fmaxf(mx1, __shfl_xor_sync(0xffffffffu, mx1, off));
        }
        const float mn0 = fmaxf(m_i[0], mx0);
        const float mn1 = fmaxf(m_i[1], mx1);
        const float cr0 = __expf(m_i[0] - mn0);
        const float cr1 = __expf(m_i[1] - mn1);
        m_i[0] = mn0; m_i[1] = mn1;

        float rs0 = 0.f, rs1 = 0.f;
        #pragma unroll
        for (int nt = 0; nt < 8; nt++) {
            sc[nt][0] = __expf(sc[nt][0] - mn0);
            sc[nt][1] = __expf(sc[nt][1] - mn0);
            sc[nt][2] = __expf(sc[nt][2] - mn1);
            sc[nt][3] = __expf(sc[nt][3] - mn1);
            rs0 += sc[nt][0] + sc[nt][1];
            rs1 += sc[nt][2] + sc[nt][3];
        }
        #pragma unroll
        for (int off = 1; off <= 2; off <<= 1) {
            rs0 += __shfl_xor_sync(0xffffffffu, rs0, off);
            rs1 += __shfl_xor_sync(0xffffffffu, rs1, off);
        }
        l_i[0] = l_i[0] * cr0 + rs0;
        l_i[1] = l_i[1] * cr1 + rs1;
        #pragma unroll
        for (int nt = 0; nt < 8; nt++) {
            O[nt][0] *= cr0; O[nt][1] *= cr0;
            O[nt][2] *= cr1; O[nt][3] *= cr1;
        }

        // ---- stage P (tf32-rounded at store; per-warp region) ----
        __syncwarp();
        #pragma unroll
        for (int nt = 0; nt < 8; nt++) {
            *reinterpret_cast<float2*>(&Psm[(wb + g8    ) * PS_STR + nt * 8 + 2 * qd]) =
                make_float2(roundtf(sc[nt][0]), roundtf(sc[nt][1]));
            *reinterpret_cast<float2*>(&Psm[(wb + g8 + 8) * PS_STR + nt * 8 + 2 * qd]) =
                make_float2(roundtf(sc[nt][2]), roundtf(sc[nt][3]));
        }
        __syncwarp();

        // ---- O += P @ V ----
        #pragma unroll
        for (int ks = 0; ks < 8; ks++) {
            unsigned afr[4];
            afr[0] = __float_as_uint(Psm[(wb + g8    ) * PS_STR + ks * 8 + qd    ]);
            afr[1] = __float_as_uint(Psm[(wb + g8 + 8) * PS_STR + ks * 8 + qd    ]);
            afr[2] = __float_as_uint(Psm[(wb + g8    ) * PS_STR + ks * 8 + qd + 4]);
            afr[3] = __float_as_uint(Psm[(wb + g8 + 8) * PS_STR + ks * 8 + qd + 4]);
            #pragma unroll
            for (int nt = 0; nt < 8; nt++) {
                const unsigned b0 = __float_as_uint(Vb[(ks * 8 + qd    ) * VS_STR + nt * 8 + g8]);
                const unsigned b1 = __float_as_uint(Vb[(ks * 8 + qd + 4) * VS_STR + nt * 8 + g8]);
                MMA_TF32(O[nt], afr, b0, b1);
            }
        }
    }

    // ---- epilogue: y = round_tf32(O / l) (consumed by tf32 proj GEMM) ----
    const float inv0 = 1.f / l_i[0];
    const float inv1 = 1.f / l_i[1];
    const size_t r0 = (size_t)b * TT + q0 + wb + g8;
    const size_t r1 = r0 + 8;
    #pragma unroll
    for (int nt = 0; nt < 8; nt++) {
        const int c = h * HD + nt * 8 + 2 * qd;
        *reinterpret_cast<float2*>(&y[r0 * CC + c]) =
            make_float2(roundtf(O[nt][0] * inv0), roundtf(O[nt][1] * inv0));
        *reinterpret_cast<float2*>(&y[r1 * CC + c]) =
            make_float2(roundtf(O[nt][2] * inv1), roundtf(O[nt][3] * inv1));
    }
}

// ---------------- launch ----------------
extern "C" void kernel_launch(void* const* d_in, const int* in_sizes, int n_in,
                              void* d_out, int out_size)
{
    const float* x      = (const float*)d_in[0];  // [B,T,C]
    const float* W_attn = (const float*)d_in[1];  // [C,3C]
    const float* b_attn = (const float*)d_in[2];  // [3C]
    const float* W_proj = (const float*)d_in[3];  // [C,C]
    const float* b_proj = (const float*)d_in[4];  // [C]
    float* out = (float*)d_out;                   // [B,T,C]

    float *qkv, *y, *xr, *wa, *wp;
    cudaGetSymbolAddress((void**)&qkv, g_qkv);
    cudaGetSymbolAddress((void**)&y,   g_y);
    cudaGetSymbolAddress((void**)&xr,  g_xr);
    cudaGetSymbolAddress((void**)&wa,  g_wa);
    cudaGetSymbolAddress((void**)&wp,  g_wp);

    cudaFuncSetAttribute(flash_attn_tf32,
                         cudaFuncAttributeMaxDynamicSharedMemorySize,
                         FLASH_SMEM_BYTES);

    const int M = BB * TT;   // 8192

    // 0) round inputs to tf32-representable fp32
    {
        const int nx = M * CC / 4, na = CC * C3 / 4, np = CC * CC / 4;
        round_tf32_kernel<<<(nx + 255) / 256, 256>>>(x, xr, nx);
        round_tf32_kernel<<<(na + 255) / 256, 256>>>(W_attn, wa, na);
        round_tf32_kernel<<<(np + 255) / 256, 256>>>(W_proj, wp, np);
    }
    // 1) qkv = xr @ wa + b_attn (tf32-rounded output)
    {
        dim3 grid(C3 / BN, M / BM);
        tf32_gemm_bias<true><<<grid, 256>>>(xr, wa, b_attn, qkv, M, C3, CC);
    }
    // 2) flash attention -> y (tf32-rounded output)
    {
        dim3 grid(TT / FBQ, NH, BB);
        flash_attn_tf32<<<grid, 256, FLASH_SMEM_BYTES>>>(qkv, y);
    }
    // 3) out = y @ wp + b_proj (full fp32 output)
    {
        dim3 grid(CC / BN, M / BM);
        tf32_gemm_bias<false><<<grid, 256>>>(y, wp, b_proj, out, M, CC, CC);
    }
}

// round 5
// speedup vs baseline: 3.3316x; 1.0005x over previous
#include <cuda_runtime.h>
#include <cuda_bf16.h>
#include <math.h>

// Problem constants
#define BB 8
#define TT 1024
#define CC 768
#define NH 12
#define HD 64
#define C3 (3*CC)   // 2304

// ---------------- scratch (no allocation allowed) ----------------
__device__ float g_qkv[BB * TT * C3];   // tf32-rounded
__device__ float g_y  [BB * TT * CC];   // tf32-rounded
__device__ float g_xr [BB * TT * CC];   // rounded x
__device__ float g_wa [CC * C3];        // rounded W_attn
__device__ float g_wp [CC * CC];        // rounded W_proj

__device__ __forceinline__ unsigned f2tf(float x) {
    unsigned r;
    asm("cvt.rna.tf32.f32 %0, %1;" : "=r"(r) : "f"(x));
    return r;
}
__device__ __forceinline__ float roundtf(float x) { return __uint_as_float(f2tf(x)); }

__device__ __forceinline__ void cp_async16(void* smem, const void* gmem) {
    unsigned s = (unsigned)__cvta_generic_to_shared(smem);
    asm volatile("cp.async.cg.shared.global [%0], [%1], 16;\n" :: "r"(s), "l"(gmem));
}

#define MMA_TF32(acc, a, b0v, b1v)                                              \
    asm volatile(                                                               \
        "mma.sync.aligned.m16n8k8.row.col.f32.tf32.tf32.f32 "                   \
        "{%0,%1,%2,%3}, {%4,%5,%6,%7}, {%8,%9}, {%0,%1,%2,%3};"                 \
        : "+f"(acc[0]), "+f"(acc[1]), "+f"(acc[2]), "+f"(acc[3])                \
        : "r"(a[0]), "r"(a[1]), "r"(a[2]), "r"(a[3]), "r"(b0v), "r"(b1v))

// ldmatrix x4 on 32-bit data: 4 regs = tf32 fragment (see theory).
#define LDSM_X4(r, addr)                                                        \
    asm volatile("ldmatrix.sync.aligned.m8n8.x4.shared.b16 {%0,%1,%2,%3}, [%4];"\
        : "=r"((r)[0]), "=r"((r)[1]), "=r"((r)[2]), "=r"((r)[3]) : "r"(addr))

// ---------------- pre-pass: round to tf32-representable fp32 ----------------
__global__ __launch_bounds__(256)
void round_tf32_kernel(const float* __restrict__ in, float* __restrict__ out, int n4)
{
    const int i = blockIdx.x * blockDim.x + threadIdx.x;
    if (i >= n4) return;
    float4 v = reinterpret_cast<const float4*>(in)[i];
    v.x = roundtf(v.x); v.y = roundtf(v.y);
    v.z = roundtf(v.z); v.w = roundtf(v.w);
    reinterpret_cast<float4*>(out)[i] = v;
}

// ================= tf32 tensor-core GEMM (inputs pre-rounded) =================
#define BM 128
#define BN 128
#define BK 16
#define AS_STRIDE (BK + 4)     // 20: LDSM rows hit disjoint bank quads
#define BS_STRIDE (BN + 8)

template <bool ROUND_OUT>
__global__ __launch_bounds__(256, 2)
void tf32_gemm_bias(const float* __restrict__ A,
                    const float* __restrict__ W,
                    const float* __restrict__ bias,
                    float* __restrict__ Cout,
                    int M, int N, int K)
{
    __shared__ float As[2][BM][AS_STRIDE];
    __shared__ float Bs[2][BK][BS_STRIDE];

    const int tid  = threadIdx.x;
    const int lane = tid & 31;
    const int warp = tid >> 5;
    const int wm   = warp >> 2;
    const int wn   = warp & 3;
    const int grp  = lane >> 2;
    const int qd   = lane & 3;
    const int m0   = blockIdx.y * BM;
    const int n0   = blockIdx.x * BN;

    const int a_row = tid >> 2;
    const int a_col = (tid & 3) * 4;
    const int b_row = tid >> 5;
    const int b_col = (tid & 31) * 4;

    // LDSM lane addressing for A fragments
    const unsigned as_base = (unsigned)__cvta_generic_to_shared(&As[0][0][0]);
    const int a_row_l = (lane & 7) + ((lane >> 3) & 1) * 8;   // m0/m2: +0, m1/m3: +8
    const int a_col_l = (lane >> 4) * 4;                      // m2/m3: +4 cols

    float acc[4][4][4] = {};

    auto load_tile = [&](int buf, int k0) {
        cp_async16(&As[buf][a_row     ][a_col], &A[(size_t)(m0 + a_row     ) * K + k0 + a_col]);
        cp_async16(&As[buf][a_row + 64][a_col], &A[(size_t)(m0 + a_row + 64) * K + k0 + a_col]);
        cp_async16(&Bs[buf][b_row    ][b_col], &W[(size_t)(k0 + b_row    ) * N + n0 + b_col]);
        cp_async16(&Bs[buf][b_row + 8][b_col], &W[(size_t)(k0 + b_row + 8) * N + n0 + b_col]);
        asm volatile("cp.async.commit_group;\n");
    };

    const int nk = K / BK;
    load_tile(0, 0);
    asm volatile("cp.async.wait_group 0;\n");
    __syncthreads();

    for (int t = 0; t < nk; t++) {
        const int buf = t & 1;
        if (t + 1 < nk) load_tile(buf ^ 1, (t + 1) * BK);

        #pragma unroll
        for (int ks = 0; ks < BK; ks += 8) {
            unsigned afr[4][4], bfr[4][2];
            #pragma unroll
            for (int mt = 0; mt < 4; mt++) {
                const unsigned addr = as_base +
                    (unsigned)(((buf * BM + wm * 64 + mt * 16 + a_row_l) * AS_STRIDE
                                + ks + a_col_l) * 4);
                LDSM_X4(afr[mt], addr);
            }
            #pragma unroll
            for (int nt = 0; nt < 4; nt++) {
                const int cb = wn * 32 + nt * 8 + grp;
                bfr[nt][0] = __float_as_uint(Bs[buf][ks + qd    ][cb]);
                bfr[nt][1] = __float_as_uint(Bs[buf][ks + qd + 4][cb]);
            }
            #pragma unroll
            for (int mt = 0; mt < 4; mt++)
                #pragma unroll
                for (int nt = 0; nt < 4; nt++)
                    MMA_TF32(acc[mt][nt], afr[mt], bfr[nt][0], bfr[nt][1]);
        }

        if (t + 1 < nk) asm volatile("cp.async.wait_group 0;\n");
        __syncthreads();
    }

    #pragma unroll
    for (int mt = 0; mt < 4; mt++) {
        const int r = m0 + wm * 64 + mt * 16 + grp;
        #pragma unroll
        for (int nt = 0; nt < 4; nt++) {
            const int c = n0 + wn * 32 + nt * 8 + qd * 2;
            const float2 bi = *reinterpret_cast<const float2*>(&bias[c]);
            float2 v0, v1;
            v0.x = acc[mt][nt][0] + bi.x;  v0.y = acc[mt][nt][1] + bi.y;
            v1.x = acc[mt][nt][2] + bi.x;  v1.y = acc[mt][nt][3] + bi.y;
            if (ROUND_OUT) {
                v0.x = roundtf(v0.x); v0.y = roundtf(v0.y);
                v1.x = roundtf(v1.x); v1.y = roundtf(v1.y);
            }
            *reinterpret_cast<float2*>(&Cout[(size_t)r       * N + c]) = v0;
            *reinterpret_cast<float2*>(&Cout[(size_t)(r + 8) * N + c]) = v1;
        }
    }
}

// ================= tf32 tensor-core flash attention (causal) =================
#define FBQ  128
#define FBKV 64
#define KS_STR 68   // 272B rows: 16B-aligned, LDSM bank-disjoint
#define VS_STR 72
#define PS_STR 68

#define OFF_K 0
#define OFF_V (2 * FBKV * KS_STR)
#define OFF_P (OFF_V + 2 * FBKV * VS_STR)
#define FLASH_SMEM_FLOATS (OFF_P + FBQ * PS_STR)
#define FLASH_SMEM_BYTES (FLASH_SMEM_FLOATS * 4)   // 106496

__global__ __launch_bounds__(256)
void flash_attn_tf32(const float* __restrict__ qkv, float* __restrict__ y)
{
    extern __shared__ float fsm[];
    float* KsBase = fsm + OFF_K;
    float* VsBase = fsm + OFF_V;
    float* Psm    = fsm + OFF_P;

    const int tid  = threadIdx.x;
    const int lane = tid & 31;
    const int warp = tid >> 5;
    const int g8   = lane >> 2;    // 0..7
    const int qd   = lane & 3;     // 0..3
    const int q0   = blockIdx.x * FBQ;
    const int h    = blockIdx.y;
    const int b    = blockIdx.z;
    const int wb   = warp * 16;

    const unsigned k_sbase = (unsigned)__cvta_generic_to_shared(KsBase);
    const unsigned p_sbase = (unsigned)__cvta_generic_to_shared(Psm);

    // LDSM lane addressing
    const int a_row_l = (lane & 7) + ((lane >> 3) & 1) * 8;  // A-operand pattern (P, Q)
    const int a_col_l = (lane >> 4) * 4;
    const int k_row_l = (lane & 7) + (lane >> 4) * 8;        // B-operand pattern (K): m2/m3 -> next 8 tokens
    const int k_col_l = ((lane >> 3) & 1) * 4;               // m1/m3 -> +4 d

    const float* base = qkv + (size_t)b * TT * C3 + h * HD;

    // ---- stage Q (scaled by exact 0.125) into per-warp P region ----
    {
        const int r0 = (lane >> 4);
        const int c  = (lane & 15) * 4;
        #pragma unroll
        for (int p = 0; p < 8; p++) {
            const int r = p * 2 + r0;
            const float4 v = *reinterpret_cast<const float4*>(
                &base[(size_t)(q0 + wb + r) * C3 + c]);
            float* d = &Psm[(wb + r) * PS_STR + c];
            d[0] = v.x * 0.125f; d[1] = v.y * 0.125f;
            d[2] = v.z * 0.125f; d[3] = v.w * 0.125f;
        }
    }
    __syncwarp();
    unsigned qfr[8][4];
    #pragma unroll
    for (int ks = 0; ks < 8; ks++) {
        const unsigned addr = p_sbase +
            (unsigned)(((wb + a_row_l) * PS_STR + ks * 8 + a_col_l) * 4);
        LDSM_X4(qfr[ks], addr);
    }

    auto load_kv = [&](int bf, int kt) {
        const int r = tid >> 4;
        const int c = (tid & 15) * 4;
        float* Kd = KsBase + bf * (FBKV * KS_STR);
        float* Vd = VsBase + bf * (FBKV * VS_STR);
        #pragma unroll
        for (int p = 0; p < 4; p++) {
            const float* rowp = base + (size_t)(kt + r + p * 16) * C3;
            cp_async16(&Kd[(r + p * 16) * KS_STR + c], rowp + CC  + c);
            cp_async16(&Vd[(r + p * 16) * VS_STR + c], rowp + 2*CC + c);
        }
        asm volatile("cp.async.commit_group;\n");
    };

    float m_i[2] = {-1e30f, -1e30f};
    float l_i[2] = {0.f, 0.f};
    float O[8][4] = {};

    const int ntiles = (q0 + FBQ) / FBKV;
    load_kv(0, 0);

    for (int t = 0; t < ntiles; t++) {
        const int buf = t & 1;
        const int kt  = t * FBKV;
        asm volatile("cp.async.wait_group 0;\n");
        __syncthreads();
        if (t + 1 < ntiles) load_kv(buf ^ 1, kt + FBKV);

        const unsigned kb_off = k_sbase + (unsigned)(buf * (FBKV * KS_STR) * 4);
        const float* Vb = VsBase + buf * (FBKV * VS_STR);

        // ---- S = Q @ K^T  (K fragments via LDSM.x4: covers token pair nt,nt+1) ----
        float sc[8][4] = {};
        #pragma unroll
        for (int ks = 0; ks < 8; ks++) {
            #pragma unroll
            for (int ntp = 0; ntp < 4; ntp++) {
                unsigned kb[4];
                const unsigned addr = kb_off +
                    (unsigned)(((ntp * 16 + k_row_l) * KS_STR + ks * 8 + k_col_l) * 4);
                LDSM_X4(kb, addr);
                MMA_TF32(sc[2*ntp    ], qfr[ks], kb[0], kb[1]);
                MMA_TF32(sc[2*ntp + 1], qfr[ks], kb[2], kb[3]);
            }
        }

        // ---- causal mask (diagonal tiles only) ----
        if (kt + FBKV > q0) {
            const int r0g = q0 + wb + g8;
            const int r1g = r0g + 8;
            #pragma unroll
            for (int nt = 0; nt < 8; nt++) {
                const int c0 = kt + nt * 8 + 2 * qd;
                if (c0     > r0g) sc[nt][0] = -1e30f;
                if (c0 + 1 > r0g) sc[nt][1] = -1e30f;
                if (c0     > r1g) sc[nt][2] = -1e30f;
                if (c0 + 1 > r1g) sc[nt][3] = -1e30f;
            }
        }

        // ---- online softmax ----
        float mx0 = -1e30f, mx1 = -1e30f;
        #pragma unroll
        for (int nt = 0; nt < 8; nt++) {
            mx0 = fmaxf(mx0, fmaxf(sc[nt][0], sc[nt][1]));
            mx1 = fmaxf(mx1, fmaxf(sc[nt][2], sc[nt][3]));
        }
        #pragma unroll
        for (int off = 1; off <= 2; off <<= 1) {
            mx0 = fmaxf(mx0, __shfl_xor_sync(0xffffffffu, mx0, off));
            mx1 = fmaxf(mx1, __shfl_xor_sync(0xffffffffu, mx1, off));
        }
        const float mn0 = fmaxf(m_i[0], mx0);
        const float mn1 = fmaxf(m_i[1], mx1);
        const float cr0 = __expf(m_i[0] - mn0);
        const float cr1 = __expf(m_i[1] - mn1);
        m_i[0] = mn0; m_i[1] = mn1;

        float rs0 = 0.f, rs1 = 0.f;
        #pragma unroll
        for (int nt = 0; nt < 8; nt++) {
            sc[nt][0] = __expf(sc[nt][0] - mn0);
            sc[nt][1] = __expf(sc[nt][1] - mn0);
            sc[nt][2] = __expf(sc[nt][2] - mn1);
            sc[nt][3] = __expf(sc[nt][3] - mn1);
            rs0 += sc[nt][0] + sc[nt][1];
            rs1 += sc[nt][2] + sc[nt][3];
        }
        #pragma unroll
        for (int off = 1; off <= 2; off <<= 1) {
            rs0 += __shfl_xor_sync(0xffffffffu, rs0, off);
            rs1 += __shfl_xor_sync(0xffffffffu, rs1, off);
        }
        l_i[0] = l_i[0] * cr0 + rs0;
        l_i[1] = l_i[1] * cr1 + rs1;
        #pragma unroll
        for (int nt = 0; nt < 8; nt++) {
            O[nt][0] *= cr0; O[nt][1] *= cr0;
            O[nt][2] *= cr1; O[nt][3] *= cr1;
        }

        // ---- stage P (tf32-rounded; per-warp region) ----
        __syncwarp();
        #pragma unroll
        for (int nt = 0; nt < 8; nt++) {
            *reinterpret_cast<float2*>(&Psm[(wb + g8    ) * PS_STR + nt * 8 + 2 * qd]) =
                make_float2(roundtf(sc[nt][0]), roundtf(sc[nt][1]));
            *reinterpret_cast<float2*>(&Psm[(wb + g8 + 8) * PS_STR + nt * 8 + 2 * qd]) =
                make_float2(roundtf(sc[nt][2]), roundtf(sc[nt][3]));
        }
        __syncwarp();

        // ---- O += P @ V  (P fragments via LDSM.x4; V scalar) ----
        #pragma unroll
        for (int ks = 0; ks < 8; ks++) {
            unsigned afr[4];
            const unsigned addr = p_sbase +
                (unsigned)(((wb + a_row_l) * PS_STR + ks * 8 + a_col_l) * 4);
            LDSM_X4(afr, addr);
            #pragma unroll
            for (int nt = 0; nt < 8; nt++) {
                const unsigned b0 = __float_as_uint(Vb[(ks * 8 + qd    ) * VS_STR + nt * 8 + g8]);
                const unsigned b1 = __float_as_uint(Vb[(ks * 8 + qd + 4) * VS_STR + nt * 8 + g8]);
                MMA_TF32(O[nt], afr, b0, b1);
            }
        }
    }

    // ---- epilogue: y = round_tf32(O / l) ----
    const float inv0 = 1.f / l_i[0];
    const float inv1 = 1.f / l_i[1];
    const size_t r0 = (size_t)b * TT + q0 + wb + g8;
    const size_t r1 = r0 + 8;
    #pragma unroll
    for (int nt = 0; nt < 8; nt++) {
        const int c = h * HD + nt * 8 + 2 * qd;
        *reinterpret_cast<float2*>(&y[r0 * CC + c]) =
            make_float2(roundtf(O[nt][0] * inv0), roundtf(O[nt][1] * inv0));
        *reinterpret_cast<float2*>(&y[r1 * CC + c]) =
            make_float2(roundtf(O[nt][2] * inv1), roundtf(O[nt][3] * inv1));
    }
}

// ---------------- launch ----------------
extern "C" void kernel_launch(void* const* d_in, const int* in_sizes, int n_in,
                              void* d_out, int out_size)
{
    const float* x      = (const float*)d_in[0];
    const float* W_attn = (const float*)d_in[1];
    const float* b_attn = (const float*)d_in[2];
    const float* W_proj = (const float*)d_in[3];
    const float* b_proj = (const float*)d_in[4];
    float* out = (float*)d_out;

    float *qkv, *y, *xr, *wa, *wp;
    cudaGetSymbolAddress((void**)&qkv, g_qkv);
    cudaGetSymbolAddress((void**)&y,   g_y);
    cudaGetSymbolAddress((void**)&xr,  g_xr);
    cudaGetSymbolAddress((void**)&wa,  g_wa);
    cudaGetSymbolAddress((void**)&wp,  g_wp);

    cudaFuncSetAttribute(flash_attn_tf32,
                         cudaFuncAttributeMaxDynamicSharedMemorySize,
                         FLASH_SMEM_BYTES);

    const int M = BB * TT;   // 8192

    // 0) round inputs to tf32-representable fp32
    {
        const int nx = M * CC / 4, na = CC * C3 / 4, np = CC * CC / 4;
        round_tf32_kernel<<<(nx + 255) / 256, 256>>>(x, xr, nx);
        round_tf32_kernel<<<(na + 255) / 256, 256>>>(W_attn, wa, na);
        round_tf32_kernel<<<(np + 255) / 256, 256>>>(W_proj, wp, np);
    }
    // 1) qkv = xr @ wa + b_attn (tf32-rounded output)
    {
        dim3 grid(C3 / BN, M / BM);
        tf32_gemm_bias<true><<<grid, 256>>>(xr, wa, b_attn, qkv, M, C3, CC);
    }
    // 2) flash attention -> y (tf32-rounded output)
    {
        dim3 grid(TT / FBQ, NH, BB);
        flash_attn_tf32<<<grid, 256, FLASH_SMEM_BYTES>>>(qkv, y);
    }
    // 3) out = y @ wp + b_proj (full fp32 output)
    {
        dim3 grid(CC / BN, M / BM);
        tf32_gemm_bias<false><<<grid, 256>>>(y, wp, b_proj, out, M, CC, CC);
    }
}

// round 6
// speedup vs baseline: 6.0930x; 1.8289x over previous
#include <cuda_runtime.h>
#include <cuda_fp16.h>
#include <math.h>

// Problem constants
#define BB 8
#define TT 1024
#define CC 768
#define NH 12
#define HD 64
#define C3 (3*CC)   // 2304

// ---------------- scratch (no allocation allowed) ----------------
__device__ __half g_qkvh[BB * TT * C3];  // fp16 qkv
__device__ __half g_yh  [BB * TT * CC];  // fp16 attention output
__device__ __half g_xh  [BB * TT * CC];  // fp16 x
__device__ __half g_wah [CC * C3];       // fp16 W_attn
__device__ __half g_wph [CC * CC];       // fp16 W_proj

__device__ __forceinline__ void cp_async16(void* smem, const void* gmem) {
    unsigned s = (unsigned)__cvta_generic_to_shared(smem);
    asm volatile("cp.async.cg.shared.global [%0], [%1], 16;\n" :: "r"(s), "l"(gmem));
}

#define MMA_F16(acc, a, b0v, b1v)                                               \
    asm volatile(                                                               \
        "mma.sync.aligned.m16n8k16.row.col.f32.f16.f16.f32 "                    \
        "{%0,%1,%2,%3}, {%4,%5,%6,%7}, {%8,%9}, {%0,%1,%2,%3};"                 \
        : "+f"(acc[0]), "+f"(acc[1]), "+f"(acc[2]), "+f"(acc[3])                \
        : "r"(a[0]), "r"(a[1]), "r"(a[2]), "r"(a[3]), "r"(b0v), "r"(b1v))

#define LDSM_X4(r, addr)                                                        \
    asm volatile("ldmatrix.sync.aligned.m8n8.x4.shared.b16 {%0,%1,%2,%3}, [%4];"\
        : "=r"((r)[0]), "=r"((r)[1]), "=r"((r)[2]), "=r"((r)[3]) : "r"(addr))

#define LDSM_X4_T(r, addr)                                                      \
    asm volatile("ldmatrix.sync.aligned.m8n8.x4.trans.shared.b16 {%0,%1,%2,%3}, [%4];"\
        : "=r"((r)[0]), "=r"((r)[1]), "=r"((r)[2]), "=r"((r)[3]) : "r"(addr))

// ---------------- pre-pass: fp32 -> fp16 ----------------
__global__ __launch_bounds__(256)
void f32_to_f16_kernel(const float* __restrict__ in, __half* __restrict__ out, int n8)
{
    const int i = blockIdx.x * blockDim.x + threadIdx.x;
    if (i >= n8) return;
    const float4 v0 = reinterpret_cast<const float4*>(in)[2*i];
    const float4 v1 = reinterpret_cast<const float4*>(in)[2*i + 1];
    __half2 h[4];
    h[0] = __floats2half2_rn(v0.x, v0.y);
    h[1] = __floats2half2_rn(v0.z, v0.w);
    h[2] = __floats2half2_rn(v1.x, v1.y);
    h[3] = __floats2half2_rn(v1.z, v1.w);
    reinterpret_cast<uint4*>(out)[i] = *reinterpret_cast<uint4*>(h);
}

// ================= fp16 tensor-core GEMM =================
// C[M,N] = A[M,K] @ W[K,N] + bias[N];  BM=BN=128, BK=32, 8 warps (2x4), warp 64x32.
#define BM 128
#define BN 128
#define BK 32
#define AS_STR 40    // halfs (80B rows: 16B aligned, LDSM rows bank-disjoint)
#define BS_STR 136   // halfs (272B rows)

template <bool HALF_OUT>
__global__ __launch_bounds__(256, 2)
void h16_gemm_bias(const __half* __restrict__ A,
                   const __half* __restrict__ W,
                   const float* __restrict__ bias,
                   void* __restrict__ CoutV,
                   int M, int N, int K)
{
    __shared__ __half As[2][BM][AS_STR];
    __shared__ __half Bs[2][BK][BS_STR];

    const int tid  = threadIdx.x;
    const int lane = tid & 31;
    const int warp = tid >> 5;
    const int wm   = warp >> 2;          // 0..1
    const int wn   = warp & 3;           // 0..3
    const int grp  = lane >> 2;          // 0..7
    const int qd   = lane & 3;           // 0..3
    const int m0   = blockIdx.y * BM;
    const int n0   = blockIdx.x * BN;

    // cp.async mapping (halfs)
    const int a_row = tid >> 2;          // 0..63 (+64)
    const int a_col = (tid & 3) * 8;     // 0,8,16,24
    const int b_row = tid >> 4;          // 0..15 (+16)
    const int b_col = (tid & 15) * 8;    // 0..120

    // ldmatrix lane addressing
    const unsigned as_base = (unsigned)__cvta_generic_to_shared(&As[0][0][0]);
    const unsigned bs_base = (unsigned)__cvta_generic_to_shared(&Bs[0][0][0]);
    const int rk_row = (lane & 7) + ((lane >> 3) & 1) * 8;  // A-plain / B-trans row
    const int rk_col = (lane >> 4) * 8;                     // +8 halfs for matrices 2,3

    float acc[4][4][4] = {};

    auto load_tile = [&](int buf, int k0) {
        cp_async16(&As[buf][a_row     ][a_col], &A[(size_t)(m0 + a_row     ) * K + k0 + a_col]);
        cp_async16(&As[buf][a_row + 64][a_col], &A[(size_t)(m0 + a_row + 64) * K + k0 + a_col]);
        cp_async16(&Bs[buf][b_row     ][b_col], &W[(size_t)(k0 + b_row     ) * N + n0 + b_col]);
        cp_async16(&Bs[buf][b_row + 16][b_col], &W[(size_t)(k0 + b_row + 16) * N + n0 + b_col]);
        asm volatile("cp.async.commit_group;\n");
    };

    const int nk = K / BK;
    load_tile(0, 0);
    asm volatile("cp.async.wait_group 0;\n");
    __syncthreads();

    for (int t = 0; t < nk; t++) {
        const int buf = t & 1;
        if (t + 1 < nk) load_tile(buf ^ 1, (t + 1) * BK);

        #pragma unroll
        for (int ks = 0; ks < BK; ks += 16) {
            unsigned afr[4][4], bfr[2][4];
            #pragma unroll
            for (int mt = 0; mt < 4; mt++) {
                const unsigned addr = as_base +
                    (unsigned)(((buf * BM + wm * 64 + mt * 16 + rk_row) * AS_STR
                                + ks + rk_col) * 2);
                LDSM_X4(afr[mt], addr);
            }
            #pragma unroll
            for (int nh = 0; nh < 2; nh++) {
                const unsigned addr = bs_base +
                    (unsigned)(((buf * BK + ks + rk_row) * BS_STR
                                + wn * 32 + nh * 16 + rk_col) * 2);
                LDSM_X4_T(bfr[nh], addr);
            }
            #pragma unroll
            for (int mt = 0; mt < 4; mt++)
                #pragma unroll
                for (int nt = 0; nt < 4; nt++) {
                    const int nh = nt >> 1, lo = (nt & 1) * 2;
                    MMA_F16(acc[mt][nt], afr[mt], bfr[nh][lo], bfr[nh][lo + 1]);
                }
        }

        if (t + 1 < nk) asm volatile("cp.async.wait_group 0;\n");
        __syncthreads();
    }

    // epilogue
    #pragma unroll
    for (int mt = 0; mt < 4; mt++) {
        const int r = m0 + wm * 64 + mt * 16 + grp;
        #pragma unroll
        for (int nt = 0; nt < 4; nt++) {
            const int c = n0 + wn * 32 + nt * 8 + qd * 2;
            const float2 bi = *reinterpret_cast<const float2*>(&bias[c]);
            const float v00 = acc[mt][nt][0] + bi.x, v01 = acc[mt][nt][1] + bi.y;
            const float v10 = acc[mt][nt][2] + bi.x, v11 = acc[mt][nt][3] + bi.y;
            if (HALF_OUT) {
                __half* Ch = (__half*)CoutV;
                *reinterpret_cast<__half2*>(&Ch[(size_t)r       * N + c]) = __floats2half2_rn(v00, v01);
                *reinterpret_cast<__half2*>(&Ch[(size_t)(r + 8) * N + c]) = __floats2half2_rn(v10, v11);
            } else {
                float* Cf = (float*)CoutV;
                *reinterpret_cast<float2*>(&Cf[(size_t)r       * N + c]) = make_float2(v00, v01);
                *reinterpret_cast<float2*>(&Cf[(size_t)(r + 8) * N + c]) = make_float2(v10, v11);
            }
        }
    }
}

// ================= fp16 tensor-core flash attention (causal) =================
// grid (TT/128, NH, BB), 256 threads (8 warps x 16 q-rows), BKV=64, double-buffered.
#define FBQ  128
#define FBKV 64
#define KS_STR 72   // halfs (144B rows)
#define VS_STR 72
#define PS_STR 72

// dynamic smem layout (halfs)
#define OFF_K 0
#define OFF_V (2 * FBKV * KS_STR)                  // 9216
#define OFF_P (OFF_V + 2 * FBKV * VS_STR)          // 18432
#define FLASH_SMEM_HALFS (OFF_P + FBQ * PS_STR)    // 27648
#define FLASH_SMEM_BYTES (FLASH_SMEM_HALFS * 2)    // 55296

__global__ __launch_bounds__(256)
void flash_attn_h16(const __half* __restrict__ qkv, __half* __restrict__ y)
{
    extern __shared__ __half hsm[];
    __half* KsBase = hsm + OFF_K;
    __half* VsBase = hsm + OFF_V;
    __half* Psm    = hsm + OFF_P;

    const int tid  = threadIdx.x;
    const int lane = tid & 31;
    const int warp = tid >> 5;
    const int g8   = lane >> 2;
    const int qd   = lane & 3;
    const int q0   = blockIdx.x * FBQ;
    const int h    = blockIdx.y;
    const int b    = blockIdx.z;
    const int wb   = warp * 16;

    const unsigned k_sbase = (unsigned)__cvta_generic_to_shared(KsBase);
    const unsigned v_sbase = (unsigned)__cvta_generic_to_shared(VsBase);
    const unsigned p_sbase = (unsigned)__cvta_generic_to_shared(Psm);

    // ldmatrix lane addressing
    const int rk_row = (lane & 7) + ((lane >> 3) & 1) * 8;  // A-plain (Q,P) / B-trans (V)
    const int rk_col = (lane >> 4) * 8;
    const int bn_row = (lane & 7) + (lane >> 4) * 8;        // K plain B-pattern (token pairs)
    const int bn_col = ((lane >> 3) & 1) * 8;

    const __half* base = qkv + (size_t)b * TT * C3 + h * HD;

    // ---- stage Q via cp.async into P region (rows 0..127) ----
    {
        const int r = tid >> 2;            // 0..63
        const int c = (tid & 3) * 16;      // 0,16,32,48 halfs
        cp_async16(&Psm[(r     ) * PS_STR + c    ], &base[(size_t)(q0 + r     ) * C3 + c    ]);
        cp_async16(&Psm[(r     ) * PS_STR + c + 8], &base[(size_t)(q0 + r     ) * C3 + c + 8]);
        cp_async16(&Psm[(r + 64) * PS_STR + c    ], &base[(size_t)(q0 + r + 64) * C3 + c    ]);
        cp_async16(&Psm[(r + 64) * PS_STR + c + 8], &base[(size_t)(q0 + r + 64) * C3 + c + 8]);
    }

    auto load_kv = [&](int bf, int kt) {
        const int r = tid >> 2;            // 0..63
        const int c = (tid & 3) * 16;
        __half* Kd = KsBase + bf * (FBKV * KS_STR);
        __half* Vd = VsBase + bf * (FBKV * VS_STR);
        const __half* rowp = base + (size_t)(kt + r) * C3;
        cp_async16(&Kd[r * KS_STR + c    ], rowp + CC   + c);
        cp_async16(&Kd[r * KS_STR + c + 8], rowp + CC   + c + 8);
        cp_async16(&Vd[r * VS_STR + c    ], rowp + 2*CC + c);
        cp_async16(&Vd[r * VS_STR + c + 8], rowp + 2*CC + c + 8);
        asm volatile("cp.async.commit_group;\n");
    };

    float m_i[2] = {-1e30f, -1e30f};
    float l_i[2] = {0.f, 0.f};
    float O[8][4] = {};
    unsigned qfr[4][4];

    const int ntiles = (q0 + FBQ) / FBKV;
    load_kv(0, 0);    // commits Q staging + first K/V as one group

    for (int t = 0; t < ntiles; t++) {
        const int buf = t & 1;
        const int kt  = t * FBKV;
        asm volatile("cp.async.wait_group 0;\n");
        __syncthreads();

        if (t == 0) {
            // build Q fragments (scale by exact 0.125 on packed halves)
            const __half2 sc2 = __floats2half2_rn(0.125f, 0.125f);
            #pragma unroll
            for (int ks = 0; ks < 4; ks++) {
                const unsigned addr = p_sbase +
                    (unsigned)(((wb + rk_row) * PS_STR + ks * 16 + rk_col) * 2);
                LDSM_X4(qfr[ks], addr);
                #pragma unroll
                for (int j = 0; j < 4; j++) {
                    __half2 hv = *reinterpret_cast<__half2*>(&qfr[ks][j]);
                    hv = __hmul2(hv, sc2);
                    qfr[ks][j] = *reinterpret_cast<unsigned*>(&hv);
                }
            }
        }
        if (t + 1 < ntiles) load_kv(buf ^ 1, kt + FBKV);

        const unsigned kb_off = k_sbase + (unsigned)(buf * (FBKV * KS_STR) * 2);
        const unsigned vb_off = v_sbase + (unsigned)(buf * (FBKV * VS_STR) * 2);

        // ---- S = Q @ K^T ----
        float scf[8][4] = {};
        #pragma unroll
        for (int ks = 0; ks < 4; ks++) {
            #pragma unroll
            for (int ntp = 0; ntp < 4; ntp++) {
                unsigned kb[4];
                const unsigned addr = kb_off +
                    (unsigned)(((ntp * 16 + bn_row) * KS_STR + ks * 16 + bn_col) * 2);
                LDSM_X4(kb, addr);
                MMA_F16(scf[2*ntp    ], qfr[ks], kb[0], kb[1]);
                MMA_F16(scf[2*ntp + 1], qfr[ks], kb[2], kb[3]);
            }
        }

        // ---- causal mask (diagonal tiles only) ----
        if (kt + FBKV > q0) {
            const int r0g = q0 + wb + g8;
            const int r1g = r0g + 8;
            #pragma unroll
            for (int nt = 0; nt < 8; nt++) {
                const int c0 = kt + nt * 8 + 2 * qd;
                if (c0     > r0g) scf[nt][0] = -1e30f;
                if (c0 + 1 > r0g) scf[nt][1] = -1e30f;
                if (c0     > r1g) scf[nt][2] = -1e30f;
                if (c0 + 1 > r1g) scf[nt][3] = -1e30f;
            }
        }

        // ---- online softmax (fp32) ----
        float mx0 = -1e30f, mx1 = -1e30f;
        #pragma unroll
        for (int nt = 0; nt < 8; nt++) {
            mx0 = fmaxf(mx0, fmaxf(scf[nt][0], scf[nt][1]));
            mx1 = fmaxf(mx1, fmaxf(scf[nt][2], scf[nt][3]));
        }
        #pragma unroll
        for (int off = 1; off <= 2; off <<= 1) {
            mx0 = fmaxf(mx0, __shfl_xor_sync(0xffffffffu, mx0, off));
            mx1 = fmaxf(mx1, __shfl_xor_sync(0xffffffffu, mx1, off));
        }
        const float mn0 = fmaxf(m_i[0], mx0);
        const float mn1 = fmaxf(m_i[1], mx1);
        const float cr0 = __expf(m_i[0] - mn0);
        const float cr1 = __expf(m_i[1] - mn1);
        m_i[0] = mn0; m_i[1] = mn1;

        float rs0 = 0.f, rs1 = 0.f;
        #pragma unroll
        for (int nt = 0; nt < 8; nt++) {
            scf[nt][0] = __expf(scf[nt][0] - mn0);
            scf[nt][1] = __expf(scf[nt][1] - mn0);
            scf[nt][2] = __expf(scf[nt][2] - mn1);
            scf[nt][3] = __expf(scf[nt][3] - mn1);
            rs0 += scf[nt][0] + scf[nt][1];
            rs1 += scf[nt][2] + scf[nt][3];
        }
        #pragma unroll
        for (int off = 1; off <= 2; off <<= 1) {
            rs0 += __shfl_xor_sync(0xffffffffu, rs0, off);
            rs1 += __shfl_xor_sync(0xffffffffu, rs1, off);
        }
        l_i[0] = l_i[0] * cr0 + rs0;
        l_i[1] = l_i[1] * cr1 + rs1;
        #pragma unroll
        for (int nt = 0; nt < 8; nt++) {
            O[nt][0] *= cr0; O[nt][1] *= cr0;
            O[nt][2] *= cr1; O[nt][3] *= cr1;
        }

        // ---- stage P as fp16 (per-warp region) ----
        __syncwarp();
        #pragma unroll
        for (int nt = 0; nt < 8; nt++) {
            *reinterpret_cast<__half2*>(&Psm[(wb + g8    ) * PS_STR + nt * 8 + 2 * qd]) =
                __floats2half2_rn(scf[nt][0], scf[nt][1]);
            *reinterpret_cast<__half2*>(&Psm[(wb + g8 + 8) * PS_STR + nt * 8 + 2 * qd]) =
                __floats2half2_rn(scf[nt][2], scf[nt][3]);
        }
        __syncwarp();

        // ---- O += P @ V ----
        #pragma unroll
        for (int ks = 0; ks < 4; ks++) {   // 16-token k-steps
            unsigned pfr[4];
            const unsigned addr = p_sbase +
                (unsigned)(((wb + rk_row) * PS_STR + ks * 16 + rk_col) * 2);
            LDSM_X4(pfr, addr);
            #pragma unroll
            for (int nh = 0; nh < 4; nh++) {   // 16-d groups
                unsigned vb[4];
                const unsigned vaddr = vb_off +
                    (unsigned)(((ks * 16 + rk_row) * VS_STR + nh * 16 + rk_col) * 2);
                LDSM_X4_T(vb, vaddr);
                MMA_F16(O[2*nh    ], pfr, vb[0], vb[1]);
                MMA_F16(O[2*nh + 1], pfr, vb[2], vb[3]);
            }
        }
    }

    // ---- epilogue: y = fp16(O / l) ----
    const float inv0 = 1.f / l_i[0];
    const float inv1 = 1.f / l_i[1];
    const size_t r0 = (size_t)b * TT + q0 + wb + g8;
    const size_t r1 = r0 + 8;
    #pragma unroll
    for (int nt = 0; nt < 8; nt++) {
        const int c = h * HD + nt * 8 + 2 * qd;
        *reinterpret_cast<__half2*>(&y[r0 * CC + c]) =
            __floats2half2_rn(O[nt][0] * inv0, O[nt][1] * inv0);
        *reinterpret_cast<__half2*>(&y[r1 * CC + c]) =
            __floats2half2_rn(O[nt][2] * inv1, O[nt][3] * inv1);
    }
}

// ---------------- launch ----------------
extern "C" void kernel_launch(void* const* d_in, const int* in_sizes, int n_in,
                              void* d_out, int out_size)
{
    const float* x      = (const float*)d_in[0];
    const float* W_attn = (const float*)d_in[1];
    const float* b_attn = (const float*)d_in[2];
    const float* W_proj = (const float*)d_in[3];
    const float* b_proj = (const float*)d_in[4];
    float* out = (float*)d_out;

    __half *qkvh, *yh, *xh, *wah, *wph;
    cudaGetSymbolAddress((void**)&qkvh, g_qkvh);
    cudaGetSymbolAddress((void**)&yh,   g_yh);
    cudaGetSymbolAddress((void**)&xh,   g_xh);
    cudaGetSymbolAddress((void**)&wah,  g_wah);
    cudaGetSymbolAddress((void**)&wph,  g_wph);

    cudaFuncSetAttribute(flash_attn_h16,
                         cudaFuncAttributeMaxDynamicSharedMemorySize,
                         FLASH_SMEM_BYTES);

    const int M = BB * TT;   // 8192

    // 0) convert inputs to fp16
    {
        const int nx = M * CC / 8, na = CC * C3 / 8, np = CC * CC / 8;
        f32_to_f16_kernel<<<(nx + 255) / 256, 256>>>(x, xh, nx);
        f32_to_f16_kernel<<<(na + 255) / 256, 256>>>(W_attn, wah, na);
        f32_to_f16_kernel<<<(np + 255) / 256, 256>>>(W_proj, wph, np);
    }
    // 1) qkv = xh @ wah + b_attn (fp16 out)
    {
        dim3 grid(C3 / BN, M / BM);
        h16_gemm_bias<true><<<grid, 256>>>(xh, wah, b_attn, qkvh, M, C3, CC);
    }
    // 2) flash attention -> yh (fp16 out)
    {
        dim3 grid(TT / FBQ, NH, BB);
        flash_attn_h16<<<grid, 256, FLASH_SMEM_BYTES>>>(qkvh, yh);
    }
    // 3) out = yh @ wph + b_proj (fp32 out)
    {
        dim3 grid(CC / BN, M / BM);
        h16_gemm_bias<false><<<grid, 256>>>(yh, wph, b_proj, out, M, CC, CC);
    }
}

// round 8
// speedup vs baseline: 6.3023x; 1.0344x over previous
#include <cuda_runtime.h>
#include <cuda_fp16.h>
#include <math.h>

// Problem constants
#define BB 8
#define TT 1024
#define CC 768
#define NH 12
#define HD 64
#define C3 (3*CC)   // 2304

// ---------------- scratch (no allocation allowed) ----------------
__device__ __half g_qkvh[BB * TT * C3];  // fp16 qkv
__device__ __half g_yh  [BB * TT * CC];  // fp16 attention output
__device__ __half g_xh  [BB * TT * CC];  // fp16 x
__device__ __half g_wah [CC * C3];       // fp16 W_attn
__device__ __half g_wph [CC * CC];       // fp16 W_proj

__device__ __forceinline__ void cp_async16(void* smem, const void* gmem) {
    unsigned s = (unsigned)__cvta_generic_to_shared(smem);
    asm volatile("cp.async.cg.shared.global [%0], [%1], 16;\n" :: "r"(s), "l"(gmem));
}

#define MMA_F16(acc, a, b0v, b1v)                                               \
    asm volatile(                                                               \
        "mma.sync.aligned.m16n8k16.row.col.f32.f16.f16.f32 "                    \
        "{%0,%1,%2,%3}, {%4,%5,%6,%7}, {%8,%9}, {%0,%1,%2,%3};"                 \
        : "+f"(acc[0]), "+f"(acc[1]), "+f"(acc[2]), "+f"(acc[3])                \
        : "r"(a[0]), "r"(a[1]), "r"(a[2]), "r"(a[3]), "r"(b0v), "r"(b1v))

#define LDSM_X4(r, addr)                                                        \
    asm volatile("ldmatrix.sync.aligned.m8n8.x4.shared.b16 {%0,%1,%2,%3}, [%4];"\
        : "=r"((r)[0]), "=r"((r)[1]), "=r"((r)[2]), "=r"((r)[3]) : "r"(addr))

#define LDSM_X4_T(r, addr)                                                      \
    asm volatile("ldmatrix.sync.aligned.m8n8.x4.trans.shared.b16 {%0,%1,%2,%3}, [%4];"\
        : "=r"((r)[0]), "=r"((r)[1]), "=r"((r)[2]), "=r"((r)[3]) : "r"(addr))

// ---------------- pre-pass: fp32 -> fp16 ----------------
__global__ __launch_bounds__(256)
void f32_to_f16_kernel(const float* __restrict__ in, __half* __restrict__ out, int n8)
{
    const int i = blockIdx.x * blockDim.x + threadIdx.x;
    if (i >= n8) return;
    const float4 v0 = reinterpret_cast<const float4*>(in)[2*i];
    const float4 v1 = reinterpret_cast<const float4*>(in)[2*i + 1];
    __half2 h[4];
    h[0] = __floats2half2_rn(v0.x, v0.y);
    h[1] = __floats2half2_rn(v0.z, v0.w);
    h[2] = __floats2half2_rn(v1.x, v1.y);
    h[3] = __floats2half2_rn(v1.z, v1.w);
    reinterpret_cast<uint4*>(out)[i] = *reinterpret_cast<uint4*>(h);
}

// ================= fp16 tensor-core GEMM (unchanged from R6) =================
#define BM 128
#define BN 128
#define BK 32
#define AS_STR 40
#define BS_STR 136

template <bool HALF_OUT>
__global__ __launch_bounds__(256, 2)
void h16_gemm_bias(const __half* __restrict__ A,
                   const __half* __restrict__ W,
                   const float* __restrict__ bias,
                   void* __restrict__ CoutV,
                   int M, int N, int K)
{
    __shared__ __half As[2][BM][AS_STR];
    __shared__ __half Bs[2][BK][BS_STR];

    const int tid  = threadIdx.x;
    const int lane = tid & 31;
    const int warp = tid >> 5;
    const int wm   = warp >> 2;
    const int wn   = warp & 3;
    const int grp  = lane >> 2;
    const int qd   = lane & 3;
    const int m0   = blockIdx.y * BM;
    const int n0   = blockIdx.x * BN;

    const int a_row = tid >> 2;
    const int a_col = (tid & 3) * 8;
    const int b_row = tid >> 4;
    const int b_col = (tid & 15) * 8;

    const unsigned as_base = (unsigned)__cvta_generic_to_shared(&As[0][0][0]);
    const unsigned bs_base = (unsigned)__cvta_generic_to_shared(&Bs[0][0][0]);
    const int rk_row = (lane & 7) + ((lane >> 3) & 1) * 8;
    const int rk_col = (lane >> 4) * 8;

    float acc[4][4][4] = {};

    auto load_tile = [&](int buf, int k0) {
        cp_async16(&As[buf][a_row     ][a_col], &A[(size_t)(m0 + a_row     ) * K + k0 + a_col]);
        cp_async16(&As[buf][a_row + 64][a_col], &A[(size_t)(m0 + a_row + 64) * K + k0 + a_col]);
        cp_async16(&Bs[buf][b_row     ][b_col], &W[(size_t)(k0 + b_row     ) * N + n0 + b_col]);
        cp_async16(&Bs[buf][b_row + 16][b_col], &W[(size_t)(k0 + b_row + 16) * N + n0 + b_col]);
        asm volatile("cp.async.commit_group;\n");
    };

    const int nk = K / BK;
    load_tile(0, 0);
    asm volatile("cp.async.wait_group 0;\n");
    __syncthreads();

    for (int t = 0; t < nk; t++) {
        const int buf = t & 1;
        if (t + 1 < nk) load_tile(buf ^ 1, (t + 1) * BK);

        #pragma unroll
        for (int ks = 0; ks < BK; ks += 16) {
            unsigned afr[4][4], bfr[2][4];
            #pragma unroll
            for (int mt = 0; mt < 4; mt++) {
                const unsigned addr = as_base +
                    (unsigned)(((buf * BM + wm * 64 + mt * 16 + rk_row) * AS_STR
                                + ks + rk_col) * 2);
                LDSM_X4(afr[mt], addr);
            }
            #pragma unroll
            for (int nh = 0; nh < 2; nh++) {
                const unsigned addr = bs_base +
                    (unsigned)(((buf * BK + ks + rk_row) * BS_STR
                                + wn * 32 + nh * 16 + rk_col) * 2);
                LDSM_X4_T(bfr[nh], addr);
            }
            #pragma unroll
            for (int mt = 0; mt < 4; mt++)
                #pragma unroll
                for (int nt = 0; nt < 4; nt++) {
                    const int nh = nt >> 1, lo = (nt & 1) * 2;
                    MMA_F16(acc[mt][nt], afr[mt], bfr[nh][lo], bfr[nh][lo + 1]);
                }
        }

        if (t + 1 < nk) asm volatile("cp.async.wait_group 0;\n");
        __syncthreads();
    }

    #pragma unroll
    for (int mt = 0; mt < 4; mt++) {
        const int r = m0 + wm * 64 + mt * 16 + grp;
        #pragma unroll
        for (int nt = 0; nt < 4; nt++) {
            const int c = n0 + wn * 32 + nt * 8 + qd * 2;
            const float2 bi = *reinterpret_cast<const float2*>(&bias[c]);
            const float v00 = acc[mt][nt][0] + bi.x, v01 = acc[mt][nt][1] + bi.y;
            const float v10 = acc[mt][nt][2] + bi.x, v11 = acc[mt][nt][3] + bi.y;
            if (HALF_OUT) {
                __half* Ch = (__half*)CoutV;
                *reinterpret_cast<__half2*>(&Ch[(size_t)r       * N + c]) = __floats2half2_rn(v00, v01);
                *reinterpret_cast<__half2*>(&Ch[(size_t)(r + 8) * N + c]) = __floats2half2_rn(v10, v11);
            } else {
                float* Cf = (float*)CoutV;
                *reinterpret_cast<float2*>(&Cf[(size_t)r       * N + c]) = make_float2(v00, v01);
                *reinterpret_cast<float2*>(&Cf[(size_t)(r + 8) * N + c]) = make_float2(v10, v11);
            }
        }
    }
}

// ================= fp16 flash attention, paired q-blocks for balance =================
// grid (TT/FBQ/2, NH, BB). Each CTA does q-block bx then q-block (NQB-1-bx):
// total KV tiles = 2(bx+1) + 2(NQB-bx) = const -> uniform work across CTAs.
#define FBQ  128
#define FBKV 64
#define NQB  (TT / FBQ)    // 8
#define KS_STR 72
#define VS_STR 72
#define PS_STR 72

#define OFF_K 0
#define OFF_V (2 * FBKV * KS_STR)
#define OFF_P (OFF_V + 2 * FBKV * VS_STR)
#define FLASH_SMEM_HALFS (OFF_P + FBQ * PS_STR)
#define FLASH_SMEM_BYTES (FLASH_SMEM_HALFS * 2)    // 55296

__global__ __launch_bounds__(256)
void flash_attn_h16(const __half* __restrict__ qkv, __half* __restrict__ y)
{
    extern __shared__ __half hsm[];
    __half* KsBase = hsm + OFF_K;
    __half* VsBase = hsm + OFF_V;
    __half* Psm    = hsm + OFF_P;

    const int tid  = threadIdx.x;
    const int lane = tid & 31;
    const int warp = tid >> 5;
    const int g8   = lane >> 2;
    const int qd   = lane & 3;
    const int h    = blockIdx.y;
    const int b    = blockIdx.z;
    const int wb   = warp * 16;

    const unsigned k_sbase = (unsigned)__cvta_generic_to_shared(KsBase);
    const unsigned v_sbase = (unsigned)__cvta_generic_to_shared(VsBase);
    const unsigned p_sbase = (unsigned)__cvta_generic_to_shared(Psm);

    const int rk_row = (lane & 7) + ((lane >> 3) & 1) * 8;
    const int rk_col = (lane >> 4) * 8;
    const int bn_row = (lane & 7) + (lane >> 4) * 8;
    const int bn_col = ((lane >> 3) & 1) * 8;

    const __half* base = qkv + (size_t)b * TT * C3 + h * HD;

    auto load_kv = [&](int bf, int kt) {
        const int r = tid >> 2;
        const int c = (tid & 3) * 16;
        __half* Kd = KsBase + bf * (FBKV * KS_STR);
        __half* Vd = VsBase + bf * (FBKV * VS_STR);
        const __half* rowp = base + (size_t)(kt + r) * C3;
        cp_async16(&Kd[r * KS_STR + c    ], rowp + CC   + c);
        cp_async16(&Kd[r * KS_STR + c + 8], rowp + CC   + c + 8);
        cp_async16(&Vd[r * VS_STR + c    ], rowp + 2*CC + c);
        cp_async16(&Vd[r * VS_STR + c + 8], rowp + 2*CC + c + 8);
        asm volatile("cp.async.commit_group;\n");
    };

    #pragma unroll 1
    for (int pass = 0; pass < 2; pass++) {
        const int qb = (pass == 0) ? (int)blockIdx.x : (NQB - 1 - (int)blockIdx.x);
        const int q0 = qb * FBQ;

        // ---- stage Q into P region ----
        {
            const int r = tid >> 2;
            const int c = (tid & 3) * 16;
            cp_async16(&Psm[(r     ) * PS_STR + c    ], &base[(size_t)(q0 + r     ) * C3 + c    ]);
            cp_async16(&Psm[(r     ) * PS_STR + c + 8], &base[(size_t)(q0 + r     ) * C3 + c + 8]);
            cp_async16(&Psm[(r + 64) * PS_STR + c    ], &base[(size_t)(q0 + r + 64) * C3 + c    ]);
            cp_async16(&Psm[(r + 64) * PS_STR + c + 8], &base[(size_t)(q0 + r + 64) * C3 + c + 8]);
        }

        float m_i[2] = {-1e30f, -1e30f};
        float l_i[2] = {0.f, 0.f};
        float O[8][4] = {};
        unsigned qfr[4][4];

        const int ntiles = (q0 + FBQ) / FBKV;
        load_kv(0, 0);   // commits Q staging + first K/V together

        for (int t = 0; t < ntiles; t++) {
            const int buf = t & 1;
            const int kt  = t * FBKV;
            asm volatile("cp.async.wait_group 0;\n");
            __syncthreads();

            if (t == 0) {
                const __half2 sc2 = __floats2half2_rn(0.125f, 0.125f);
                #pragma unroll
                for (int ks = 0; ks < 4; ks++) {
                    const unsigned addr = p_sbase +
                        (unsigned)(((wb + rk_row) * PS_STR + ks * 16 + rk_col) * 2);
                    LDSM_X4(qfr[ks], addr);
                    #pragma unroll
                    for (int j = 0; j < 4; j++) {
                        __half2 hv = *reinterpret_cast<__half2*>(&qfr[ks][j]);
                        hv = __hmul2(hv, sc2);
                        qfr[ks][j] = *reinterpret_cast<unsigned*>(&hv);
                    }
                }
            }
            if (t + 1 < ntiles) load_kv(buf ^ 1, kt + FBKV);

            const unsigned kb_off = k_sbase + (unsigned)(buf * (FBKV * KS_STR) * 2);
            const unsigned vb_off = v_sbase + (unsigned)(buf * (FBKV * VS_STR) * 2);

            // ---- S = Q @ K^T ----
            float scf[8][4] = {};
            #pragma unroll
            for (int ks = 0; ks < 4; ks++) {
                #pragma unroll
                for (int ntp = 0; ntp < 4; ntp++) {
                    unsigned kb[4];
                    const unsigned addr = kb_off +
                        (unsigned)(((ntp * 16 + bn_row) * KS_STR + ks * 16 + bn_col) * 2);
                    LDSM_X4(kb, addr);
                    MMA_F16(scf[2*ntp    ], qfr[ks], kb[0], kb[1]);
                    MMA_F16(scf[2*ntp + 1], qfr[ks], kb[2], kb[3]);
                }
            }

            // ---- causal mask (diagonal tiles only) ----
            if (kt + FBKV > q0) {
                const int r0g = q0 + wb + g8;
                const int r1g = r0g + 8;
                #pragma unroll
                for (int nt = 0; nt < 8; nt++) {
                    const int c0 = kt + nt * 8 + 2 * qd;
                    if (c0     > r0g) scf[nt][0] = -1e30f;
                    if (c0 + 1 > r0g) scf[nt][1] = -1e30f;
                    if (c0     > r1g) scf[nt][2] = -1e30f;
                    if (c0 + 1 > r1g) scf[nt][3] = -1e30f;
                }
            }

            // ---- online softmax ----
            float mx0 = -1e30f, mx1 = -1e30f;
            #pragma unroll
            for (int nt = 0; nt < 8; nt++) {
                mx0 = fmaxf(mx0, fmaxf(scf[nt][0], scf[nt][1]));
                mx1 = fmaxf(mx1, fmaxf(scf[nt][2], scf[nt][3]));
            }
            #pragma unroll
            for (int off = 1; off <= 2; off <<= 1) {
                mx0 = fmaxf(mx0, __shfl_xor_sync(0xffffffffu, mx0, off));
                mx1 = fmaxf(mx1, __shfl_xor_sync(0xffffffffu, mx1, off));
            }
            const float mn0 = fmaxf(m_i[0], mx0);
            const float mn1 = fmaxf(m_i[1], mx1);
            const float cr0 = __expf(m_i[0] - mn0);
            const float cr1 = __expf(m_i[1] - mn1);
            m_i[0] = mn0; m_i[1] = mn1;

            float rs0 = 0.f, rs1 = 0.f;
            #pragma unroll
            for (int nt = 0; nt < 8; nt++) {
                scf[nt][0] = __expf(scf[nt][0] - mn0);
                scf[nt][1] = __expf(scf[nt][1] - mn0);
                scf[nt][2] = __expf(scf[nt][2] - mn1);
                scf[nt][3] = __expf(scf[nt][3] - mn1);
                rs0 += scf[nt][0] + scf[nt][1];
                rs1 += scf[nt][2] + scf[nt][3];
            }
            #pragma unroll
            for (int off = 1; off <= 2; off <<= 1) {
                rs0 += __shfl_xor_sync(0xffffffffu, rs0, off);
                rs1 += __shfl_xor_sync(0xffffffffu, rs1, off);
            }
            l_i[0] = l_i[0] * cr0 + rs0;
            l_i[1] = l_i[1] * cr1 + rs1;
            #pragma unroll
            for (int nt = 0; nt < 8; nt++) {
                O[nt][0] *= cr0; O[nt][1] *= cr0;
                O[nt][2] *= cr1; O[nt][3] *= cr1;
            }

            // ---- stage P as fp16 (per-warp region) ----
            __syncwarp();
            #pragma unroll
            for (int nt = 0; nt < 8; nt++) {
                *reinterpret_cast<__half2*>(&Psm[(wb + g8    ) * PS_STR + nt * 8 + 2 * qd]) =
                    __floats2half2_rn(scf[nt][0], scf[nt][1]);
                *reinterpret_cast<__half2*>(&Psm[(wb + g8 + 8) * PS_STR + nt * 8 + 2 * qd]) =
                    __floats2half2_rn(scf[nt][2], scf[nt][3]);
            }
            __syncwarp();

            // ---- O += P @ V ----
            #pragma unroll
            for (int ks = 0; ks < 4; ks++) {
                unsigned pfr[4];
                const unsigned addr = p_sbase +
                    (unsigned)(((wb + rk_row) * PS_STR + ks * 16 + rk_col) * 2);
                LDSM_X4(pfr, addr);
                #pragma unroll
                for (int nh = 0; nh < 4; nh++) {
                    unsigned vb[4];
                    const unsigned vaddr = vb_off +
                        (unsigned)(((ks * 16 + rk_row) * VS_STR + nh * 16 + rk_col) * 2);
                    LDSM_X4_T(vb, vaddr);
                    MMA_F16(O[2*nh    ], pfr, vb[0], vb[1]);
                    MMA_F16(O[2*nh + 1], pfr, vb[2], vb[3]);
                }
            }
        }

        // ---- epilogue for this q-block ----
        const float inv0 = 1.f / l_i[0];
        const float inv1 = 1.f / l_i[1];
        const size_t r0 = (size_t)b * TT + q0 + wb + g8;
        const size_t r1 = r0 + 8;
        #pragma unroll
        for (int nt = 0; nt < 8; nt++) {
            const int c = h * HD + nt * 8 + 2 * qd;
            *reinterpret_cast<__half2*>(&y[r0 * CC + c]) =
                __floats2half2_rn(O[nt][0] * inv0, O[nt][1] * inv0);
            *reinterpret_cast<__half2*>(&y[r1 * CC + c]) =
                __floats2half2_rn(O[nt][2] * inv1, O[nt][3] * inv1);
        }

        __syncthreads();   // Psm/Ks/Vs safe to reuse for second pass
    }
}

// ---------------- launch ----------------
extern "C" void kernel_launch(void* const* d_in, const int* in_sizes, int n_in,
                              void* d_out, int out_size)
{
    const float* x      = (const float*)d_in[0];
    const float* W_attn = (const float*)d_in[1];
    const float* b_attn = (const float*)d_in[2];
    const float* W_proj = (const float*)d_in[3];
    const float* b_proj = (const float*)d_in[4];
    float* out = (float*)d_out;

    __half *qkvh, *yh, *xh, *wah, *wph;
    cudaGetSymbolAddress((void**)&qkvh, g_qkvh);
    cudaGetSymbolAddress((void**)&yh,   g_yh);
    cudaGetSymbolAddress((void**)&xh,   g_xh);
    cudaGetSymbolAddress((void**)&wah,  g_wah);
    cudaGetSymbolAddress((void**)&wph,  g_wph);

    cudaFuncSetAttribute(flash_attn_h16,
                         cudaFuncAttributeMaxDynamicSharedMemorySize,
                         FLASH_SMEM_BYTES);

    const int M = BB * TT;   // 8192

    // 0) convert inputs to fp16
    {
        const int nx = M * CC / 8, na = CC * C3 / 8, np = CC * CC / 8;
        f32_to_f16_kernel<<<(nx + 255) / 256, 256>>>(x, xh, nx);
        f32_to_f16_kernel<<<(na + 255) / 256, 256>>>(W_attn, wah, na);
        f32_to_f16_kernel<<<(np + 255) / 256, 256>>>(W_proj, wph, np);
    }
    // 1) qkv = xh @ wah + b_attn (fp16 out)
    {
        dim3 grid(C3 / BN, M / BM);
        h16_gemm_bias<true><<<grid, 256>>>(xh, wah, b_attn, qkvh, M, C3, CC);
    }
    // 2) flash attention -> yh (paired q-blocks)
    {
        dim3 grid(TT / FBQ / 2, NH, BB);   // (4, 12, 8)
        flash_attn_h16<<<grid, 256, FLASH_SMEM_BYTES>>>(qkvh, yh);
    }
    // 3) out = yh @ wph + b_proj (fp32 out)
    {
        dim3 grid(CC / BN, M / BM);
        h16_gemm_bias<false><<<grid, 256>>>(yh, wph, b_proj, out, M, CC, CC);
    }
}

// round 9
// speedup vs baseline: 6.3485x; 1.0073x over previous
#include <cuda_runtime.h>
#include <cuda_fp16.h>
#include <math.h>

// Problem constants
#define BB 8
#define TT 1024
#define CC 768
#define NH 12
#define HD 64
#define C3 (3*CC)   // 2304

#define LOG2E 1.4426950408889634f

// ---------------- scratch (no allocation allowed) ----------------
__device__ __half g_qkvh[BB * TT * C3];  // fp16 qkv
__device__ __half g_yh  [BB * TT * CC];  // fp16 attention output
__device__ __half g_xh  [BB * TT * CC];  // fp16 x
__device__ __half g_wah [CC * C3];       // fp16 W_attn
__device__ __half g_wph [CC * CC];       // fp16 W_proj

__device__ __forceinline__ void cp_async16(void* smem, const void* gmem) {
    unsigned s = (unsigned)__cvta_generic_to_shared(smem);
    asm volatile("cp.async.cg.shared.global [%0], [%1], 16;\n" :: "r"(s), "l"(gmem));
}

__device__ __forceinline__ float ex2f(float x) {
    float r; asm("ex2.approx.f32 %0, %1;" : "=f"(r) : "f"(x)); return r;
}
__device__ __forceinline__ unsigned h2ex2(unsigned x) {
    unsigned r; asm("ex2.approx.f16x2 %0, %1;" : "=r"(r) : "r"(x)); return r;
}
__device__ __forceinline__ unsigned pack_h2(float lo, float hi) {
    __half2 h = __floats2half2_rn(lo, hi);
    return *reinterpret_cast<unsigned*>(&h);
}

#define MMA_F16(acc, a, b0v, b1v)                                               \
    asm volatile(                                                               \
        "mma.sync.aligned.m16n8k16.row.col.f32.f16.f16.f32 "                    \
        "{%0,%1,%2,%3}, {%4,%5,%6,%7}, {%8,%9}, {%0,%1,%2,%3};"                 \
        : "+f"(acc[0]), "+f"(acc[1]), "+f"(acc[2]), "+f"(acc[3])                \
        : "r"(a[0]), "r"(a[1]), "r"(a[2]), "r"(a[3]), "r"(b0v), "r"(b1v))

#define LDSM_X4(r, addr)                                                        \
    asm volatile("ldmatrix.sync.aligned.m8n8.x4.shared.b16 {%0,%1,%2,%3}, [%4];"\
        : "=r"((r)[0]), "=r"((r)[1]), "=r"((r)[2]), "=r"((r)[3]) : "r"(addr))

#define LDSM_X4_T(r, addr)                                                      \
    asm volatile("ldmatrix.sync.aligned.m8n8.x4.trans.shared.b16 {%0,%1,%2,%3}, [%4];"\
        : "=r"((r)[0]), "=r"((r)[1]), "=r"((r)[2]), "=r"((r)[3]) : "r"(addr))

// ---------------- pre-pass: fp32 -> fp16 ----------------
__global__ __launch_bounds__(256)
void f32_to_f16_kernel(const float* __restrict__ in, __half* __restrict__ out, int n8)
{
    const int i = blockIdx.x * blockDim.x + threadIdx.x;
    if (i >= n8) return;
    const float4 v0 = reinterpret_cast<const float4*>(in)[2*i];
    const float4 v1 = reinterpret_cast<const float4*>(in)[2*i + 1];
    __half2 h[4];
    h[0] = __floats2half2_rn(v0.x, v0.y);
    h[1] = __floats2half2_rn(v0.z, v0.w);
    h[2] = __floats2half2_rn(v1.x, v1.y);
    h[3] = __floats2half2_rn(v1.z, v1.w);
    reinterpret_cast<uint4*>(out)[i] = *reinterpret_cast<uint4*>(h);
}

// ================= fp16 tensor-core GEMM (unchanged) =================
#define BM 128
#define BN 128
#define BK 32
#define AS_STR 40
#define BS_STR 136

template <bool HALF_OUT>
__global__ __launch_bounds__(256, 2)
void h16_gemm_bias(const __half* __restrict__ A,
                   const __half* __restrict__ W,
                   const float* __restrict__ bias,
                   void* __restrict__ CoutV,
                   int M, int N, int K)
{
    __shared__ __half As[2][BM][AS_STR];
    __shared__ __half Bs[2][BK][BS_STR];

    const int tid  = threadIdx.x;
    const int lane = tid & 31;
    const int warp = tid >> 5;
    const int wm   = warp >> 2;
    const int wn   = warp & 3;
    const int grp  = lane >> 2;
    const int qd   = lane & 3;
    const int m0   = blockIdx.y * BM;
    const int n0   = blockIdx.x * BN;

    const int a_row = tid >> 2;
    const int a_col = (tid & 3) * 8;
    const int b_row = tid >> 4;
    const int b_col = (tid & 15) * 8;

    const unsigned as_base = (unsigned)__cvta_generic_to_shared(&As[0][0][0]);
    const unsigned bs_base = (unsigned)__cvta_generic_to_shared(&Bs[0][0][0]);
    const int rk_row = (lane & 7) + ((lane >> 3) & 1) * 8;
    const int rk_col = (lane >> 4) * 8;

    float acc[4][4][4] = {};

    auto load_tile = [&](int buf, int k0) {
        cp_async16(&As[buf][a_row     ][a_col], &A[(size_t)(m0 + a_row     ) * K + k0 + a_col]);
        cp_async16(&As[buf][a_row + 64][a_col], &A[(size_t)(m0 + a_row + 64) * K + k0 + a_col]);
        cp_async16(&Bs[buf][b_row     ][b_col], &W[(size_t)(k0 + b_row     ) * N + n0 + b_col]);
        cp_async16(&Bs[buf][b_row + 16][b_col], &W[(size_t)(k0 + b_row + 16) * N + n0 + b_col]);
        asm volatile("cp.async.commit_group;\n");
    };

    const int nk = K / BK;
    load_tile(0, 0);
    asm volatile("cp.async.wait_group 0;\n");
    __syncthreads();

    for (int t = 0; t < nk; t++) {
        const int buf = t & 1;
        if (t + 1 < nk) load_tile(buf ^ 1, (t + 1) * BK);

        #pragma unroll
        for (int ks = 0; ks < BK; ks += 16) {
            unsigned afr[4][4], bfr[2][4];
            #pragma unroll
            for (int mt = 0; mt < 4; mt++) {
                const unsigned addr = as_base +
                    (unsigned)(((buf * BM + wm * 64 + mt * 16 + rk_row) * AS_STR
                                + ks + rk_col) * 2);
                LDSM_X4(afr[mt], addr);
            }
            #pragma unroll
            for (int nh = 0; nh < 2; nh++) {
                const unsigned addr = bs_base +
                    (unsigned)(((buf * BK + ks + rk_row) * BS_STR
                                + wn * 32 + nh * 16 + rk_col) * 2);
                LDSM_X4_T(bfr[nh], addr);
            }
            #pragma unroll
            for (int mt = 0; mt < 4; mt++)
                #pragma unroll
                for (int nt = 0; nt < 4; nt++) {
                    const int nh = nt >> 1, lo = (nt & 1) * 2;
                    MMA_F16(acc[mt][nt], afr[mt], bfr[nh][lo], bfr[nh][lo + 1]);
                }
        }

        if (t + 1 < nk) asm volatile("cp.async.wait_group 0;\n");
        __syncthreads();
    }

    #pragma unroll
    for (int mt = 0; mt < 4; mt++) {
        const int r = m0 + wm * 64 + mt * 16 + grp;
        #pragma unroll
        for (int nt = 0; nt < 4; nt++) {
            const int c = n0 + wn * 32 + nt * 8 + qd * 2;
            const float2 bi = *reinterpret_cast<const float2*>(&bias[c]);
            const float v00 = acc[mt][nt][0] + bi.x, v01 = acc[mt][nt][1] + bi.y;
            const float v10 = acc[mt][nt][2] + bi.x, v11 = acc[mt][nt][3] + bi.y;
            if (HALF_OUT) {
                __half* Ch = (__half*)CoutV;
                *reinterpret_cast<__half2*>(&Ch[(size_t)r       * N + c]) = __floats2half2_rn(v00, v01);
                *reinterpret_cast<__half2*>(&Ch[(size_t)(r + 8) * N + c]) = __floats2half2_rn(v10, v11);
            } else {
                float* Cf = (float*)CoutV;
                *reinterpret_cast<float2*>(&Cf[(size_t)r       * N + c]) = make_float2(v00, v01);
                *reinterpret_cast<float2*>(&Cf[(size_t)(r + 8) * N + c]) = make_float2(v10, v11);
            }
        }
    }
}

// ================= fp16 flash attention, paired q-blocks =================
#define FBQ  128
#define FBKV 64
#define NQB  (TT / FBQ)    // 8
#define KS_STR 72
#define VS_STR 72
#define PS_STR 72

#define OFF_K 0
#define OFF_V (2 * FBKV * KS_STR)
#define OFF_P (OFF_V + 2 * FBKV * VS_STR)
#define FLASH_SMEM_HALFS (OFF_P + FBQ * PS_STR)
#define FLASH_SMEM_BYTES (FLASH_SMEM_HALFS * 2)    // 55296

#define ONES_H2 0x3C003C00u

__global__ __launch_bounds__(256)
void flash_attn_h16(const __half* __restrict__ qkv, __half* __restrict__ y)
{
    extern __shared__ __half hsm[];
    __half* KsBase = hsm + OFF_K;
    __half* VsBase = hsm + OFF_V;
    __half* Psm    = hsm + OFF_P;

    const int tid  = threadIdx.x;
    const int lane = tid & 31;
    const int warp = tid >> 5;
    const int g8   = lane >> 2;
    const int qd   = lane & 3;
    const int h    = blockIdx.y;
    const int b    = blockIdx.z;
    const int wb   = warp * 16;

    const unsigned k_sbase = (unsigned)__cvta_generic_to_shared(KsBase);
    const unsigned v_sbase = (unsigned)__cvta_generic_to_shared(VsBase);
    const unsigned p_sbase = (unsigned)__cvta_generic_to_shared(Psm);

    const int rk_row = (lane & 7) + ((lane >> 3) & 1) * 8;
    const int rk_col = (lane >> 4) * 8;
    const int bn_row = (lane & 7) + (lane >> 4) * 8;
    const int bn_col = ((lane >> 3) & 1) * 8;

    const __half* base = qkv + (size_t)b * TT * C3 + h * HD;

    auto load_kv = [&](int bf, int kt) {
        const int r = tid >> 2;
        const int c = (tid & 3) * 16;
        __half* Kd = KsBase + bf * (FBKV * KS_STR);
        __half* Vd = VsBase + bf * (FBKV * VS_STR);
        const __half* rowp = base + (size_t)(kt + r) * C3;
        cp_async16(&Kd[r * KS_STR + c    ], rowp + CC   + c);
        cp_async16(&Kd[r * KS_STR + c + 8], rowp + CC   + c + 8);
        cp_async16(&Vd[r * VS_STR + c    ], rowp + 2*CC + c);
        cp_async16(&Vd[r * VS_STR + c + 8], rowp + 2*CC + c + 8);
        asm volatile("cp.async.commit_group;\n");
    };

    #pragma unroll 1
    for (int pass = 0; pass < 2; pass++) {
        const int qb = (pass == 0) ? (int)blockIdx.x : (NQB - 1 - (int)blockIdx.x);
        const int q0 = qb * FBQ;

        // ---- stage Q into P region ----
        {
            const int r = tid >> 2;
            const int c = (tid & 3) * 16;
            cp_async16(&Psm[(r     ) * PS_STR + c    ], &base[(size_t)(q0 + r     ) * C3 + c    ]);
            cp_async16(&Psm[(r     ) * PS_STR + c + 8], &base[(size_t)(q0 + r     ) * C3 + c + 8]);
            cp_async16(&Psm[(r + 64) * PS_STR + c    ], &base[(size_t)(q0 + r + 64) * C3 + c    ]);
            cp_async16(&Psm[(r + 64) * PS_STR + c + 8], &base[(size_t)(q0 + r + 64) * C3 + c + 8]);
        }

        float m_i[2] = {-1e30f, -1e30f};
        float l_i[2] = {0.f, 0.f};
        float O[8][4] = {};
        unsigned qfr[4][4];

        const int ntiles = (q0 + FBQ) / FBKV;
        load_kv(0, 0);   // commits Q staging + first K/V together

        for (int t = 0; t < ntiles; t++) {
            const int buf = t & 1;
            const int kt  = t * FBKV;
            asm volatile("cp.async.wait_group 0;\n");
            __syncthreads();

            if (t == 0) {
                const __half2 sc2 = __floats2half2_rn(0.125f, 0.125f);
                #pragma unroll
                for (int ks = 0; ks < 4; ks++) {
                    const unsigned addr = p_sbase +
                        (unsigned)(((wb + rk_row) * PS_STR + ks * 16 + rk_col) * 2);
                    LDSM_X4(qfr[ks], addr);
                    #pragma unroll
                    for (int j = 0; j < 4; j++) {
                        __half2 hv = *reinterpret_cast<__half2*>(&qfr[ks][j]);
                        hv = __hmul2(hv, sc2);
                        qfr[ks][j] = *reinterpret_cast<unsigned*>(&hv);
                    }
                }
            }
            if (t + 1 < ntiles) load_kv(buf ^ 1, kt + FBKV);

            const unsigned kb_off = k_sbase + (unsigned)(buf * (FBKV * KS_STR) * 2);
            const unsigned vb_off = v_sbase + (unsigned)(buf * (FBKV * VS_STR) * 2);

            // ---- S = Q @ K^T ----
            float scf[8][4] = {};
            #pragma unroll
            for (int ks = 0; ks < 4; ks++) {
                #pragma unroll
                for (int ntp = 0; ntp < 4; ntp++) {
                    unsigned kb[4];
                    const unsigned addr = kb_off +
                        (unsigned)(((ntp * 16 + bn_row) * KS_STR + ks * 16 + bn_col) * 2);
                    LDSM_X4(kb, addr);
                    MMA_F16(scf[2*ntp    ], qfr[ks], kb[0], kb[1]);
                    MMA_F16(scf[2*ntp + 1], qfr[ks], kb[2], kb[3]);
                }
            }

            // ---- causal mask (diagonal tiles only) ----
            if (kt + FBKV > q0) {
                const int r0g = q0 + wb + g8;
                const int r1g = r0g + 8;
                #pragma unroll
                for (int nt = 0; nt < 8; nt++) {
                    const int c0 = kt + nt * 8 + 2 * qd;
                    if (c0     > r0g) scf[nt][0] = -1e30f;
                    if (c0 + 1 > r0g) scf[nt][1] = -1e30f;
                    if (c0     > r1g) scf[nt][2] = -1e30f;
                    if (c0 + 1 > r1g) scf[nt][3] = -1e30f;
                }
            }

            // ---- row max ----
            float mx0 = -1e30f, mx1 = -1e30f;
            #pragma unroll
            for (int nt = 0; nt < 8; nt++) {
                mx0 = fmaxf(mx0, fmaxf(scf[nt][0], scf[nt][1]));
                mx1 = fmaxf(mx1, fmaxf(scf[nt][2], scf[nt][3]));
            }
            #pragma unroll
            for (int off = 1; off <= 2; off <<= 1) {
                mx0 = fmaxf(mx0, __shfl_xor_sync(0xffffffffu, mx0, off));
                mx1 = fmaxf(mx1, __shfl_xor_sync(0xffffffffu, mx1, off));
            }
            const float mn0 = fmaxf(m_i[0], mx0);
            const float mn1 = fmaxf(m_i[1], mx1);
            const float mn0L = mn0 * LOG2E;
            const float mn1L = mn1 * LOG2E;
            const float cr0 = ex2f(fmaf(m_i[0], LOG2E, -mn0L));
            const float cr1 = ex2f(fmaf(m_i[1], LOG2E, -mn1L));
            m_i[0] = mn0; m_i[1] = mn1;

            // ---- P = exp2((S - m)*log2e) in packed fp16; store to Psm ----
            __syncwarp();
            #pragma unroll
            for (int nt = 0; nt < 8; nt++) {
                const unsigned p0 = h2ex2(pack_h2(fmaf(scf[nt][0], LOG2E, -mn0L),
                                                  fmaf(scf[nt][1], LOG2E, -mn0L)));
                const unsigned p1 = h2ex2(pack_h2(fmaf(scf[nt][2], LOG2E, -mn1L),
                                                  fmaf(scf[nt][3], LOG2E, -mn1L)));
                *reinterpret_cast<unsigned*>(&Psm[(wb + g8    ) * PS_STR + nt * 8 + 2 * qd]) = p0;
                *reinterpret_cast<unsigned*>(&Psm[(wb + g8 + 8) * PS_STR + nt * 8 + 2 * qd]) = p1;
            }
            __syncwarp();

            // ---- O *= corr ----
            #pragma unroll
            for (int nt = 0; nt < 8; nt++) {
                O[nt][0] *= cr0; O[nt][1] *= cr0;
                O[nt][2] *= cr1; O[nt][3] *= cr1;
            }

            // ---- O += P @ V ; row sums l via ones-column MMA ----
            float lacc[4] = {0.f, 0.f, 0.f, 0.f};
            #pragma unroll
            for (int ks = 0; ks < 4; ks++) {
                unsigned pfr[4];
                const unsigned addr = p_sbase +
                    (unsigned)(((wb + rk_row) * PS_STR + ks * 16 + rk_col) * 2);
                LDSM_X4(pfr, addr);
                MMA_F16(lacc, pfr, ONES_H2, ONES_H2);
                #pragma unroll
                for (int nh = 0; nh < 4; nh++) {
                    unsigned vb[4];
                    const unsigned vaddr = vb_off +
                        (unsigned)(((ks * 16 + rk_row) * VS_STR + nh * 16 + rk_col) * 2);
                    LDSM_X4_T(vb, vaddr);
                    MMA_F16(O[2*nh    ], pfr, vb[0], vb[1]);
                    MMA_F16(O[2*nh + 1], pfr, vb[2], vb[3]);
                }
            }
            l_i[0] = l_i[0] * cr0 + lacc[0];
            l_i[1] = l_i[1] * cr1 + lacc[2];
        }

        // ---- epilogue for this q-block ----
        const float inv0 = 1.f / l_i[0];
        const float inv1 = 1.f / l_i[1];
        const size_t r0 = (size_t)b * TT + q0 + wb + g8;
        const size_t r1 = r0 + 8;
        #pragma unroll
        for (int nt = 0; nt < 8; nt++) {
            const int c = h * HD + nt * 8 + 2 * qd;
            *reinterpret_cast<__half2*>(&y[r0 * CC + c]) =
                __floats2half2_rn(O[nt][0] * inv0, O[nt][1] * inv0);
            *reinterpret_cast<__half2*>(&y[r1 * CC + c]) =
                __floats2half2_rn(O[nt][2] * inv1, O[nt][3] * inv1);
        }

        __syncthreads();   // smem safe to reuse for second pass
    }
}

// ---------------- launch ----------------
extern "C" void kernel_launch(void* const* d_in, const int* in_sizes, int n_in,
                              void* d_out, int out_size)
{
    const float* x      = (const float*)d_in[0];
    const float* W_attn = (const float*)d_in[1];
    const float* b_attn = (const float*)d_in[2];
    const float* W_proj = (const float*)d_in[3];
    const float* b_proj = (const float*)d_in[4];
    float* out = (float*)d_out;

    __half *qkvh, *yh, *xh, *wah, *wph;
    cudaGetSymbolAddress((void**)&qkvh, g_qkvh);
    cudaGetSymbolAddress((void**)&yh,   g_yh);
    cudaGetSymbolAddress((void**)&xh,   g_xh);
    cudaGetSymbolAddress((void**)&wah,  g_wah);
    cudaGetSymbolAddress((void**)&wph,  g_wph);

    cudaFuncSetAttribute(flash_attn_h16,
                         cudaFuncAttributeMaxDynamicSharedMemorySize,
                         FLASH_SMEM_BYTES);

    const int M = BB * TT;   // 8192

    // 0) convert inputs to fp16
    {
        const int nx = M * CC / 8, na = CC * C3 / 8, np = CC * CC / 8;
        f32_to_f16_kernel<<<(nx + 255) / 256, 256>>>(x, xh, nx);
        f32_to_f16_kernel<<<(na + 255) / 256, 256>>>(W_attn, wah, na);
        f32_to_f16_kernel<<<(np + 255) / 256, 256>>>(W_proj, wph, np);
    }
    // 1) qkv = xh @ wah + b_attn (fp16 out)
    {
        dim3 grid(C3 / BN, M / BM);
        h16_gemm_bias<true><<<grid, 256>>>(xh, wah, b_attn, qkvh, M, C3, CC);
    }
    // 2) flash attention -> yh (paired q-blocks)
    {
        dim3 grid(TT / FBQ / 2, NH, BB);   // (4, 12, 8)
        flash_attn_h16<<<grid, 256, FLASH_SMEM_BYTES>>>(qkvh, yh);
    }
    // 3) out = yh @ wph + b_proj (fp32 out)
    {
        dim3 grid(CC / BN, M / BM);
        h16_gemm_bias<false><<<grid, 256>>>(yh, wph, b_proj, out, M, CC, CC);
    }
}

// round 10
// speedup vs baseline: 6.7585x; 1.0646x over previous
#include <cuda_runtime.h>
#include <cuda_fp16.h>
#include <math.h>

// Problem constants
#define BB 8
#define TT 1024
#define CC 768
#define NH 12
#define HD 64
#define C3 (3*CC)   // 2304

#define LOG2E 1.4426950408889634f

// ---------------- scratch (no allocation allowed) ----------------
__device__ __half g_qkvh[BB * TT * C3];  // fp16 qkv
__device__ __half g_yh  [BB * TT * CC];  // fp16 attention output
__device__ __half g_xh  [BB * TT * CC];  // fp16 x
__device__ __half g_wah [CC * C3];       // fp16 W_attn
__device__ __half g_wph [CC * CC];       // fp16 W_proj

__device__ __forceinline__ void cp_async16(void* smem, const void* gmem) {
    unsigned s = (unsigned)__cvta_generic_to_shared(smem);
    asm volatile("cp.async.cg.shared.global [%0], [%1], 16;\n" :: "r"(s), "l"(gmem));
}

__device__ __forceinline__ float ex2f(float x) {
    float r; asm("ex2.approx.f32 %0, %1;" : "=f"(r) : "f"(x)); return r;
}
__device__ __forceinline__ unsigned h2ex2(unsigned x) {
    unsigned r; asm("ex2.approx.f16x2 %0, %1;" : "=r"(r) : "r"(x)); return r;
}
__device__ __forceinline__ unsigned pack_h2(float lo, float hi) {
    __half2 h = __floats2half2_rn(lo, hi);
    return *reinterpret_cast<unsigned*>(&h);
}

#define MMA_F16(acc, a, b0v, b1v)                                               \
    asm volatile(                                                               \
        "mma.sync.aligned.m16n8k16.row.col.f32.f16.f16.f32 "                    \
        "{%0,%1,%2,%3}, {%4,%5,%6,%7}, {%8,%9}, {%0,%1,%2,%3};"                 \
        : "+f"(acc[0]), "+f"(acc[1]), "+f"(acc[2]), "+f"(acc[3])                \
        : "r"(a[0]), "r"(a[1]), "r"(a[2]), "r"(a[3]), "r"(b0v), "r"(b1v))

#define LDSM_X4(r, addr)                                                        \
    asm volatile("ldmatrix.sync.aligned.m8n8.x4.shared.b16 {%0,%1,%2,%3}, [%4];"\
        : "=r"((r)[0]), "=r"((r)[1]), "=r"((r)[2]), "=r"((r)[3]) : "r"(addr))

#define LDSM_X4_T(r, addr)                                                      \
    asm volatile("ldmatrix.sync.aligned.m8n8.x4.trans.shared.b16 {%0,%1,%2,%3}, [%4];"\
        : "=r"((r)[0]), "=r"((r)[1]), "=r"((r)[2]), "=r"((r)[3]) : "r"(addr))

// ---------------- merged pre-pass: fp32 -> fp16 for x, W_attn, W_proj ----------------
#define NX8 (BB * TT * CC / 8)   // 786432
#define NA8 (CC * C3 / 8)        // 221184
#define NP8 (CC * CC / 8)        // 73728

__global__ __launch_bounds__(256)
void prep_f16_kernel(const float* __restrict__ x,  const float* __restrict__ wa,
                     const float* __restrict__ wp,
                     __half* __restrict__ xh, __half* __restrict__ wah,
                     __half* __restrict__ wph)
{
    int i = blockIdx.x * blockDim.x + threadIdx.x;
    const float* in; __half* out;
    if (i < NX8)             { in = x;  out = xh;  }
    else if (i < NX8 + NA8)  { in = wa; out = wah; i -= NX8; }
    else if (i < NX8 + NA8 + NP8) { in = wp; out = wph; i -= NX8 + NA8; }
    else return;
    const float4 v0 = reinterpret_cast<const float4*>(in)[2*i];
    const float4 v1 = reinterpret_cast<const float4*>(in)[2*i + 1];
    __half2 h[4];
    h[0] = __floats2half2_rn(v0.x, v0.y);
    h[1] = __floats2half2_rn(v0.z, v0.w);
    h[2] = __floats2half2_rn(v1.x, v1.y);
    h[3] = __floats2half2_rn(v1.z, v1.w);
    reinterpret_cast<uint4*>(out)[i] = *reinterpret_cast<uint4*>(h);
}

// ================= fp16 tensor-core GEMM (unchanged) =================
#define BM 128
#define BN 128
#define BK 32
#define AS_STR 40
#define BS_STR 136

template <bool HALF_OUT>
__global__ __launch_bounds__(256, 2)
void h16_gemm_bias(const __half* __restrict__ A,
                   const __half* __restrict__ W,
                   const float* __restrict__ bias,
                   void* __restrict__ CoutV,
                   int M, int N, int K)
{
    __shared__ __half As[2][BM][AS_STR];
    __shared__ __half Bs[2][BK][BS_STR];

    const int tid  = threadIdx.x;
    const int lane = tid & 31;
    const int warp = tid >> 5;
    const int wm   = warp >> 2;
    const int wn   = warp & 3;
    const int grp  = lane >> 2;
    const int qd   = lane & 3;
    const int m0   = blockIdx.y * BM;
    const int n0   = blockIdx.x * BN;

    const int a_row = tid >> 2;
    const int a_col = (tid & 3) * 8;
    const int b_row = tid >> 4;
    const int b_col = (tid & 15) * 8;

    const unsigned as_base = (unsigned)__cvta_generic_to_shared(&As[0][0][0]);
    const unsigned bs_base = (unsigned)__cvta_generic_to_shared(&Bs[0][0][0]);
    const int rk_row = (lane & 7) + ((lane >> 3) & 1) * 8;
    const int rk_col = (lane >> 4) * 8;

    float acc[4][4][4] = {};

    auto load_tile = [&](int buf, int k0) {
        cp_async16(&As[buf][a_row     ][a_col], &A[(size_t)(m0 + a_row     ) * K + k0 + a_col]);
        cp_async16(&As[buf][a_row + 64][a_col], &A[(size_t)(m0 + a_row + 64) * K + k0 + a_col]);
        cp_async16(&Bs[buf][b_row     ][b_col], &W[(size_t)(k0 + b_row     ) * N + n0 + b_col]);
        cp_async16(&Bs[buf][b_row + 16][b_col], &W[(size_t)(k0 + b_row + 16) * N + n0 + b_col]);
        asm volatile("cp.async.commit_group;\n");
    };

    const int nk = K / BK;
    load_tile(0, 0);
    asm volatile("cp.async.wait_group 0;\n");
    __syncthreads();

    for (int t = 0; t < nk; t++) {
        const int buf = t & 1;
        if (t + 1 < nk) load_tile(buf ^ 1, (t + 1) * BK);

        #pragma unroll
        for (int ks = 0; ks < BK; ks += 16) {
            unsigned afr[4][4], bfr[2][4];
            #pragma unroll
            for (int mt = 0; mt < 4; mt++) {
                const unsigned addr = as_base +
                    (unsigned)(((buf * BM + wm * 64 + mt * 16 + rk_row) * AS_STR
                                + ks + rk_col) * 2);
                LDSM_X4(afr[mt], addr);
            }
            #pragma unroll
            for (int nh = 0; nh < 2; nh++) {
                const unsigned addr = bs_base +
                    (unsigned)(((buf * BK + ks + rk_row) * BS_STR
                                + wn * 32 + nh * 16 + rk_col) * 2);
                LDSM_X4_T(bfr[nh], addr);
            }
            #pragma unroll
            for (int mt = 0; mt < 4; mt++)
                #pragma unroll
                for (int nt = 0; nt < 4; nt++) {
                    const int nh = nt >> 1, lo = (nt & 1) * 2;
                    MMA_F16(acc[mt][nt], afr[mt], bfr[nh][lo], bfr[nh][lo + 1]);
                }
        }

        if (t + 1 < nk) asm volatile("cp.async.wait_group 0;\n");
        __syncthreads();
    }

    #pragma unroll
    for (int mt = 0; mt < 4; mt++) {
        const int r = m0 + wm * 64 + mt * 16 + grp;
        #pragma unroll
        for (int nt = 0; nt < 4; nt++) {
            const int c = n0 + wn * 32 + nt * 8 + qd * 2;
            const float2 bi = *reinterpret_cast<const float2*>(&bias[c]);
            const float v00 = acc[mt][nt][0] + bi.x, v01 = acc[mt][nt][1] + bi.y;
            const float v10 = acc[mt][nt][2] + bi.x, v11 = acc[mt][nt][3] + bi.y;
            if (HALF_OUT) {
                __half* Ch = (__half*)CoutV;
                *reinterpret_cast<__half2*>(&Ch[(size_t)r       * N + c]) = __floats2half2_rn(v00, v01);
                *reinterpret_cast<__half2*>(&Ch[(size_t)(r + 8) * N + c]) = __floats2half2_rn(v10, v11);
            } else {
                float* Cf = (float*)CoutV;
                *reinterpret_cast<float2*>(&Cf[(size_t)r       * N + c]) = make_float2(v00, v01);
                *reinterpret_cast<float2*>(&Cf[(size_t)(r + 8) * N + c]) = make_float2(v10, v11);
            }
        }
    }
}

// ================= fp16 flash attention: paired q-blocks, register-resident P =================
#define FBQ  128
#define FBKV 64
#define NQB  (TT / FBQ)    // 8
#define KS_STR 72
#define VS_STR 72
#define QS_STR 72

#define OFF_K 0
#define OFF_V (2 * FBKV * KS_STR)
#define OFF_Q (OFF_V + 2 * FBKV * VS_STR)
#define FLASH_SMEM_HALFS (OFF_Q + FBQ * QS_STR)
#define FLASH_SMEM_BYTES (FLASH_SMEM_HALFS * 2)    // 55296

#define ONES_H2 0x3C003C00u

__global__ __launch_bounds__(256)
void flash_attn_h16(const __half* __restrict__ qkv, __half* __restrict__ y)
{
    extern __shared__ __half hsm[];
    __half* KsBase = hsm + OFF_K;
    __half* VsBase = hsm + OFF_V;
    __half* Qsm    = hsm + OFF_Q;

    const int tid  = threadIdx.x;
    const int lane = tid & 31;
    const int warp = tid >> 5;
    const int g8   = lane >> 2;
    const int qd   = lane & 3;
    const int h    = blockIdx.y;
    const int b    = blockIdx.z;
    const int wb   = warp * 16;

    const unsigned k_sbase = (unsigned)__cvta_generic_to_shared(KsBase);
    const unsigned v_sbase = (unsigned)__cvta_generic_to_shared(VsBase);
    const unsigned q_sbase = (unsigned)__cvta_generic_to_shared(Qsm);

    const int rk_row = (lane & 7) + ((lane >> 3) & 1) * 8;   // A-plain (Q) / B-trans (V)
    const int rk_col = (lane >> 4) * 8;
    const int bn_row = (lane & 7) + (lane >> 4) * 8;         // K plain B-pattern
    const int bn_col = ((lane >> 3) & 1) * 8;

    const __half* base = qkv + (size_t)b * TT * C3 + h * HD;

    auto load_kv = [&](int bf, int kt) {
        const int r = tid >> 2;
        const int c = (tid & 3) * 16;
        __half* Kd = KsBase + bf * (FBKV * KS_STR);
        __half* Vd = VsBase + bf * (FBKV * VS_STR);
        const __half* rowp = base + (size_t)(kt + r) * C3;
        cp_async16(&Kd[r * KS_STR + c    ], rowp + CC   + c);
        cp_async16(&Kd[r * KS_STR + c + 8], rowp + CC   + c + 8);
        cp_async16(&Vd[r * VS_STR + c    ], rowp + 2*CC + c);
        cp_async16(&Vd[r * VS_STR + c + 8], rowp + 2*CC + c + 8);
        asm volatile("cp.async.commit_group;\n");
    };

    #pragma unroll 1
    for (int pass = 0; pass < 2; pass++) {
        const int qb = (pass == 0) ? (int)blockIdx.x : (NQB - 1 - (int)blockIdx.x);
        const int q0 = qb * FBQ;

        // ---- stage Q ----
        {
            const int r = tid >> 2;
            const int c = (tid & 3) * 16;
            cp_async16(&Qsm[(r     ) * QS_STR + c    ], &base[(size_t)(q0 + r     ) * C3 + c    ]);
            cp_async16(&Qsm[(r     ) * QS_STR + c + 8], &base[(size_t)(q0 + r     ) * C3 + c + 8]);
            cp_async16(&Qsm[(r + 64) * QS_STR + c    ], &base[(size_t)(q0 + r + 64) * C3 + c    ]);
            cp_async16(&Qsm[(r + 64) * QS_STR + c + 8], &base[(size_t)(q0 + r + 64) * C3 + c + 8]);
        }

        float m_i[2] = {-1e30f, -1e30f};
        float l_i[2] = {0.f, 0.f};
        float O[8][4] = {};
        unsigned qfr[4][4];

        const int ntiles = (q0 + FBQ) / FBKV;
        load_kv(0, 0);   // commits Q staging + first K/V together

        for (int t = 0; t < ntiles; t++) {
            const int buf = t & 1;
            const int kt  = t * FBKV;
            asm volatile("cp.async.wait_group 0;\n");
            __syncthreads();

            if (t == 0) {
                const __half2 sc2 = __floats2half2_rn(0.125f, 0.125f);
                #pragma unroll
                for (int ks = 0; ks < 4; ks++) {
                    const unsigned addr = q_sbase +
                        (unsigned)(((wb + rk_row) * QS_STR + ks * 16 + rk_col) * 2);
                    LDSM_X4(qfr[ks], addr);
                    #pragma unroll
                    for (int j = 0; j < 4; j++) {
                        __half2 hv = *reinterpret_cast<__half2*>(&qfr[ks][j]);
                        hv = __hmul2(hv, sc2);
                        qfr[ks][j] = *reinterpret_cast<unsigned*>(&hv);
                    }
                }
            }
            if (t + 1 < ntiles) load_kv(buf ^ 1, kt + FBKV);

            const unsigned kb_off = k_sbase + (unsigned)(buf * (FBKV * KS_STR) * 2);
            const unsigned vb_off = v_sbase + (unsigned)(buf * (FBKV * VS_STR) * 2);

            // ---- S = Q @ K^T ----
            float scf[8][4] = {};
            #pragma unroll
            for (int ks = 0; ks < 4; ks++) {
                #pragma unroll
                for (int ntp = 0; ntp < 4; ntp++) {
                    unsigned kb[4];
                    const unsigned addr = kb_off +
                        (unsigned)(((ntp * 16 + bn_row) * KS_STR + ks * 16 + bn_col) * 2);
                    LDSM_X4(kb, addr);
                    MMA_F16(scf[2*ntp    ], qfr[ks], kb[0], kb[1]);
                    MMA_F16(scf[2*ntp + 1], qfr[ks], kb[2], kb[3]);
                }
            }

            // ---- causal mask (diagonal tiles only) ----
            if (kt + FBKV > q0) {
                const int r0g = q0 + wb + g8;
                const int r1g = r0g + 8;
                #pragma unroll
                for (int nt = 0; nt < 8; nt++) {
                    const int c0 = kt + nt * 8 + 2 * qd;
                    if (c0     > r0g) scf[nt][0] = -1e30f;
                    if (c0 + 1 > r0g) scf[nt][1] = -1e30f;
                    if (c0     > r1g) scf[nt][2] = -1e30f;
                    if (c0 + 1 > r1g) scf[nt][3] = -1e30f;
                }
            }

            // ---- row max ----
            float mx0 = -1e30f, mx1 = -1e30f;
            #pragma unroll
            for (int nt = 0; nt < 8; nt++) {
                mx0 = fmaxf(mx0, fmaxf(scf[nt][0], scf[nt][1]));
                mx1 = fmaxf(mx1, fmaxf(scf[nt][2], scf[nt][3]));
            }
            #pragma unroll
            for (int off = 1; off <= 2; off <<= 1) {
                mx0 = fmaxf(mx0, __shfl_xor_sync(0xffffffffu, mx0, off));
                mx1 = fmaxf(mx1, __shfl_xor_sync(0xffffffffu, mx1, off));
            }
            const float mn0 = fmaxf(m_i[0], mx0);
            const float mn1 = fmaxf(m_i[1], mx1);
            const float mn0L = mn0 * LOG2E;
            const float mn1L = mn1 * LOG2E;
            const float cr0 = ex2f(fmaf(m_i[0], LOG2E, -mn0L));
            const float cr1 = ex2f(fmaf(m_i[1], LOG2E, -mn1L));
            m_i[0] = mn0; m_i[1] = mn1;

            // ---- P = exp2(S·log2e − m·log2e), built DIRECTLY as PV A-fragments ----
            // S C-layout == PV A-layout: a0/a1 from tile 2ks (k=2qd), a2/a3 from 2ks+1 (k=2qd+8)
            unsigned pfr[4][4];
            #pragma unroll
            for (int ks = 0; ks < 4; ks++) {
                pfr[ks][0] = h2ex2(pack_h2(fmaf(scf[2*ks  ][0], LOG2E, -mn0L),
                                           fmaf(scf[2*ks  ][1], LOG2E, -mn0L)));
                pfr[ks][1] = h2ex2(pack_h2(fmaf(scf[2*ks  ][2], LOG2E, -mn1L),
                                           fmaf(scf[2*ks  ][3], LOG2E, -mn1L)));
                pfr[ks][2] = h2ex2(pack_h2(fmaf(scf[2*ks+1][0], LOG2E, -mn0L),
                                           fmaf(scf[2*ks+1][1], LOG2E, -mn0L)));
                pfr[ks][3] = h2ex2(pack_h2(fmaf(scf[2*ks+1][2], LOG2E, -mn1L),
                                           fmaf(scf[2*ks+1][3], LOG2E, -mn1L)));
            }

            // ---- O *= corr ----
            #pragma unroll
            for (int nt = 0; nt < 8; nt++) {
                O[nt][0] *= cr0; O[nt][1] *= cr0;
                O[nt][2] *= cr1; O[nt][3] *= cr1;
            }

            // ---- O += P @ V ; row sums l via ones-column MMA ----
            float lacc[4] = {0.f, 0.f, 0.f, 0.f};
            #pragma unroll
            for (int ks = 0; ks < 4; ks++) {
                MMA_F16(lacc, pfr[ks], ONES_H2, ONES_H2);
                #pragma unroll
                for (int nh = 0; nh < 4; nh++) {
                    unsigned vb[4];
                    const unsigned vaddr = vb_off +
                        (unsigned)(((ks * 16 + rk_row) * VS_STR + nh * 16 + rk_col) * 2);
                    LDSM_X4_T(vb, vaddr);
                    MMA_F16(O[2*nh    ], pfr[ks], vb[0], vb[1]);
                    MMA_F16(O[2*nh + 1], pfr[ks], vb[2], vb[3]);
                }
            }
            l_i[0] = l_i[0] * cr0 + lacc[0];
            l_i[1] = l_i[1] * cr1 + lacc[2];
        }

        // ---- epilogue for this q-block ----
        const float inv0 = 1.f / l_i[0];
        const float inv1 = 1.f / l_i[1];
        const size_t r0 = (size_t)b * TT + q0 + wb + g8;
        const size_t r1 = r0 + 8;
        #pragma unroll
        for (int nt = 0; nt < 8; nt++) {
            const int c = h * HD + nt * 8 + 2 * qd;
            *reinterpret_cast<__half2*>(&y[r0 * CC + c]) =
                __floats2half2_rn(O[nt][0] * inv0, O[nt][1] * inv0);
            *reinterpret_cast<__half2*>(&y[r1 * CC + c]) =
                __floats2half2_rn(O[nt][2] * inv1, O[nt][3] * inv1);
        }

        __syncthreads();   // smem safe to reuse for second pass
    }
}

// ---------------- launch ----------------
extern "C" void kernel_launch(void* const* d_in, const int* in_sizes, int n_in,
                              void* d_out, int out_size)
{
    const float* x      = (const float*)d_in[0];
    const float* W_attn = (const float*)d_in[1];
    const float* b_attn = (const float*)d_in[2];
    const float* W_proj = (const float*)d_in[3];
    const float* b_proj = (const float*)d_in[4];
    float* out = (float*)d_out;

    __half *qkvh, *yh, *xh, *wah, *wph;
    cudaGetSymbolAddress((void**)&qkvh, g_qkvh);
    cudaGetSymbolAddress((void**)&yh,   g_yh);
    cudaGetSymbolAddress((void**)&xh,   g_xh);
    cudaGetSymbolAddress((void**)&wah,  g_wah);
    cudaGetSymbolAddress((void**)&wph,  g_wph);

    cudaFuncSetAttribute(flash_attn_h16,
                         cudaFuncAttributeMaxDynamicSharedMemorySize,
                         FLASH_SMEM_BYTES);

    const int M = BB * TT;   // 8192

    // 0) convert inputs to fp16 (single merged launch)
    {
        const int ntot = NX8 + NA8 + NP8;
        prep_f16_kernel<<<(ntot + 255) / 256, 256>>>(x, W_attn, W_proj, xh, wah, wph);
    }
    // 1) qkv = xh @ wah + b_attn (fp16 out)
    {
        dim3 grid(C3 / BN, M / BM);
        h16_gemm_bias<true><<<grid, 256>>>(xh, wah, b_attn, qkvh, M, C3, CC);
    }
    // 2) flash attention -> yh (paired q-blocks, register P)
    {
        dim3 grid(TT / FBQ / 2, NH, BB);   // (4, 12, 8)
        flash_attn_h16<<<grid, 256, FLASH_SMEM_BYTES>>>(qkvh, yh);
    }
    // 3) out = yh @ wph + b_proj (fp32 out)
    {
        dim3 grid(CC / BN, M / BM);
        h16_gemm_bias<false><<<grid, 256>>>(yh, wph, b_proj, out, M, CC, CC);
    }
}